// round 11
// baseline (speedup 1.0000x reference)
#include <cuda_runtime.h>
#include <cuda_bf16.h>
#include <cstdint>
#include <math.h>

#define BB 4
#define NN 4096
#define DD 256
#define KTOP 64
#define EPSN 1e-12f

#define PACKW 512             // [hi(256) | lo(256)] per row
#define NCHUNK_V 12           // value: full 3-term split
#define NCHUNK_C 8            // cos: H·(H+L)^T
#define CAP 768               // candidate buffer per row

// ---------------- scratch ----------------
__device__ __nv_bfloat16  g_value[(size_t)BB * NN * DD];
__device__ float          g_cos  [(size_t)BB * NN * NN];          // lower-triangle orientation only
__device__ uint16_t       g_key16[(size_t)BB * NN * NN];          // u16 keys, both orientations
__device__ __nv_bfloat16  g_pack [(size_t)BB * NN * PACKW];
__device__ __nv_bfloat16  g_Wpack[(size_t)DD * PACKW];
__device__ float          g_norm [(size_t)BB * NN];
__device__ float          g_xsum_part[BB * 16 * DD];
__device__ float          g_sumv[BB * DD];

__device__ __constant__ int CAMAP_V[NCHUNK_V] = {0,1,2,3, 0,1,2,3, 4,5,6,7};
__device__ __constant__ int CBMAP_V[NCHUNK_V] = {0,1,2,3, 4,5,6,7, 0,1,2,3};

__device__ __forceinline__ uint32_t smem_to_u32(const void* p) {
    uint32_t a;
    asm("{ .reg .u64 t; cvta.to.shared.u64 t, %1; cvt.u32.u64 %0, t; }" : "=r"(a) : "l"(p));
    return a;
}
__device__ __forceinline__ void ldsm4(uint32_t& r0, uint32_t& r1, uint32_t& r2, uint32_t& r3, uint32_t addr) {
    asm volatile("ldmatrix.sync.aligned.m8n8.x4.shared.b16 {%0,%1,%2,%3}, [%4];"
        : "=r"(r0), "=r"(r1), "=r"(r2), "=r"(r3) : "r"(addr));
}
__device__ __forceinline__ void mma16816(float* d, const uint32_t* a, const uint32_t* b) {
    asm volatile("mma.sync.aligned.m16n8k16.row.col.f32.bf16.bf16.f32 "
        "{%0,%1,%2,%3}, {%4,%5,%6,%7}, {%8,%9}, {%0,%1,%2,%3};"
        : "+f"(d[0]), "+f"(d[1]), "+f"(d[2]), "+f"(d[3])
        : "r"(a[0]), "r"(a[1]), "r"(a[2]), "r"(a[3]), "r"(b[0]), "r"(b[1]));
}
__device__ __forceinline__ void cp_async16(uint32_t saddr, const void* gptr) {
    asm volatile("cp.async.cg.shared.global [%0], [%1], 16;" :: "r"(saddr), "l"(gptr) : "memory");
}
#define CP_COMMIT() asm volatile("cp.async.commit_group;" ::: "memory")
#define CP_WAIT(N)  asm volatile("cp.async.wait_group %0;" :: "n"(N) : "memory")

__device__ __forceinline__ uint32_t key32_of_bits(uint32_t x) {
    return (x & 0x80000000u) ? ~x : (x | 0x80000000u);
}
__device__ __forceinline__ uint32_t key16_of(float v) {
    return key32_of_bits(__float_as_uint(v)) >> 16;
}

// ---------------- 1) normalize + hi/lo pack + norm save (+ W pack piggyback) ----------------
__global__ void __launch_bounds__(DD) normalize_pack_kernel(const float* __restrict__ x,
                                                            const float* __restrict__ W)
{
    int row = blockIdx.x;
    int d   = threadIdx.x;
    float v = x[(size_t)row * DD + d];
    float s = v * v;
    __shared__ float red[8];
    #pragma unroll
    for (int o = 16; o; o >>= 1) s += __shfl_xor_sync(0xffffffffu, s, o);
    if ((d & 31) == 0) red[d >> 5] = s;
    __syncthreads();
    if (d < 32) {
        float t = (d < 8) ? red[d] : 0.f;
        #pragma unroll
        for (int o = 4; o; o >>= 1) t += __shfl_xor_sync(0xffffffffu, t, o);
        if (d == 0) red[0] = t;
    }
    __syncthreads();
    float norm = sqrtf(red[0]);
    float nv = v / fmaxf(norm, EPSN);

    __nv_bfloat16 hi = __float2bfloat16(nv);
    __nv_bfloat16 lo = __float2bfloat16(nv - __bfloat162float(hi));

    size_t base = (size_t)row * PACKW;
    g_pack[base + d]       = hi;
    g_pack[base + 256 + d] = lo;
    if (d == 0) g_norm[row] = norm;

    if (row < DD) {
        float w = W[(size_t)row * DD + d];
        __nv_bfloat16 whi = __float2bfloat16(w);
        __nv_bfloat16 wlo = __float2bfloat16(w - __bfloat162float(whi));
        g_Wpack[(size_t)row * PACKW + d]       = whi;
        g_Wpack[(size_t)row * PACKW + 256 + d] = wlo;
    }
}

// ---------------- 1b) per-batch partial column sums of x ----------------
__global__ void __launch_bounds__(DD) xsum_part_kernel(const float* __restrict__ x)
{
    int b = blockIdx.y, c = blockIdx.x, e = threadIdx.x;
    const float* base = x + (size_t)b * NN * DD + (size_t)c * 256 * DD + e;
    float s = 0.f;
    #pragma unroll 8
    for (int n = 0; n < 256; n++) s += base[(size_t)n * DD];
    g_xsum_part[(b * 16 + c) * DD + e] = s;
}

// ---------------- 1c) sumv = (colsum x) @ W^T + N*b  (exact algebra) ----------------
__global__ void __launch_bounds__(DD) sumv_mv_kernel(const float* __restrict__ W,
                                                     const float* __restrict__ bias)
{
    int b = blockIdx.x, t = threadIdx.x;
    __shared__ float xs[DD];
    float s = 0.f;
    #pragma unroll
    for (int c = 0; c < 16; c++) s += g_xsum_part[(b * 16 + c) * DD + t];
    xs[t] = s;
    __syncthreads();
    float acc = 0.f;
    const float4* Wr = (const float4*)&W[(size_t)t * DD];
    #pragma unroll 8
    for (int d4 = 0; d4 < 64; d4++) {
        float4 w = Wr[d4];
        acc += xs[d4 * 4 + 0] * w.x + xs[d4 * 4 + 1] * w.y
             + xs[d4 * 4 + 2] * w.z + xs[d4 * 4 + 3] * w.w;
    }
    g_sumv[b * DD + t] = acc + (float)NN * bias[t];
}

// ---------------- 2) value = norm * (nx @ W^T) + b  -> bf16 ----------------
__global__ void __launch_bounds__(256, 2) valuemma_kernel(const float* __restrict__ bias)
{
    extern __shared__ char smem[];
    const uint32_t sb = smem_to_u32(smem);

    const int tid  = threadIdx.x;
    const int wid  = tid >> 5;
    const int lane = tid & 31;
    const int wm   = wid & 3;
    const int wn   = wid >> 2;
    const int m0   = blockIdx.y * 128;
    const int n0   = blockIdx.x * 128;

    const __nv_bfloat16* Agl = g_pack  + (size_t)m0 * PACKW;
    const __nv_bfloat16* Bgl = g_Wpack + (size_t)n0 * PACKW;

    const int lr = tid >> 3;
    const int lj = tid & 7;

    auto load_chunk_async = [&](int c, int s) {
        const char* ga = (const char*)Agl + (size_t)CAMAP_V[c] * 128;
        const char* gb = (const char*)Bgl + (size_t)CBMAP_V[c] * 128;
        uint32_t sa = sb + s * 32768;
        uint32_t sbm = sa + 16384;
        #pragma unroll
        for (int k = 0; k < 4; k++) {
            int r = lr + 32 * k;
            uint32_t off = r * 128 + ((lj ^ (r & 7)) << 4);
            cp_async16(sa + off,  ga + (size_t)r * (PACKW * 2) + lj * 16);
            cp_async16(sbm + off, gb + (size_t)r * (PACKW * 2) + lj * 16);
        }
    };

    float acc[2][8][4];
    #pragma unroll
    for (int ia = 0; ia < 2; ia++)
        #pragma unroll
        for (int j = 0; j < 8; j++)
            #pragma unroll
            for (int q = 0; q < 4; q++) acc[ia][j][q] = 0.f;

    const int arow_lo = (lane & 7) + ((lane >> 3) & 1) * 8;
    const int a_cc_add = (lane >> 4);
    const int brow_lo = (lane & 7) + ((lane >> 4) ? 8 : 0);
    const int b_cc_add = ((lane >> 3) & 1);

    load_chunk_async(0, 0); CP_COMMIT();
    load_chunk_async(1, 1); CP_COMMIT();

    for (int c = 0; c < NCHUNK_V; c++) {
        if (c + 1 < NCHUNK_V) { CP_WAIT(1); } else { CP_WAIT(0); }
        __syncthreads();
        if (c + 2 < NCHUNK_V) { load_chunk_async(c + 2, (c + 2) % 3); CP_COMMIT(); }

        const uint32_t abase = sb + (c % 3) * 32768;
        const uint32_t bbase = abase + 16384;

        #pragma unroll
        for (int ks = 0; ks < 4; ks++) {
            uint32_t af[2][4], bf[8][2];
            #pragma unroll
            for (int ia = 0; ia < 2; ia++) {
                int row = wm * 32 + ia * 16 + arow_lo;
                uint32_t cc = 2 * ks + a_cc_add;
                uint32_t addr = abase + row * 128 + ((cc << 4) ^ ((row & 7) << 4));
                ldsm4(af[ia][0], af[ia][1], af[ia][2], af[ia][3], addr);
            }
            #pragma unroll
            for (int L = 0; L < 4; L++) {
                int row = wn * 64 + L * 16 + brow_lo;
                uint32_t cc = 2 * ks + b_cc_add;
                uint32_t addr = bbase + row * 128 + ((cc << 4) ^ ((row & 7) << 4));
                ldsm4(bf[2 * L][0], bf[2 * L][1], bf[2 * L + 1][0], bf[2 * L + 1][1], addr);
            }
            #pragma unroll
            for (int ia = 0; ia < 2; ia++)
                #pragma unroll
                for (int j = 0; j < 8; j++)
                    mma16816(acc[ia][j], af[ia], bf[j]);
        }
    }

    const int g = lane >> 2, q = lane & 3;
    #pragma unroll
    for (int ia = 0; ia < 2; ia++) {
        int row = m0 + wm * 32 + ia * 16 + g;
        float nr0 = __ldg(&g_norm[row]);
        float nr8 = __ldg(&g_norm[row + 8]);
        #pragma unroll
        for (int j = 0; j < 8; j++) {
            int col = n0 + wn * 64 + j * 8 + q * 2;
            float b0 = __ldg(&bias[col]), b1 = __ldg(&bias[col + 1]);
            __nv_bfloat162 v01 = __floats2bfloat162_rn(acc[ia][j][0] * nr0 + b0, acc[ia][j][1] * nr0 + b1);
            __nv_bfloat162 v23 = __floats2bfloat162_rn(acc[ia][j][2] * nr8 + b0, acc[ia][j][3] * nr8 + b1);
            *(__nv_bfloat162*)&g_value[(size_t)row * DD + col]       = v01;
            *(__nv_bfloat162*)&g_value[(size_t)(row + 8) * DD + col] = v23;
        }
    }
}

// ---------------- 4) cos = H @ (H+L)^T ; fp32 tile-orientation only + u16 keys both orientations ----------------
__global__ void __launch_bounds__(256, 2) cosmma_kernel(float* __restrict__ C, uint16_t* __restrict__ K16)
{
    extern __shared__ char smem[];
    const uint32_t sb = smem_to_u32(smem);

    const int tid  = threadIdx.x;
    const int wid  = tid >> 5;
    const int lane = tid & 31;
    const int wm   = wid & 3;
    const int wn   = wid >> 2;
    const int b    = blockIdx.z;

    int i  = blockIdx.x;
    int by = (int)((sqrtf(8.f * (float)i + 1.f) - 1.f) * 0.5f);
    while ((by + 1) * (by + 2) / 2 <= i) by++;
    while (by * (by + 1) / 2 > i) by--;
    int bx = i - by * (by + 1) / 2;
    const int m0 = by * 128;
    const int n0 = bx * 128;

    const __nv_bfloat16* Agl = g_pack + ((size_t)b * NN + m0) * PACKW;
    const __nv_bfloat16* Bgl = g_pack + ((size_t)b * NN + n0) * PACKW;

    const int lr = tid >> 3;
    const int lj = tid & 7;

    auto load_chunk_async = [&](int c, int s) {
        const char* ga = (const char*)Agl + (size_t)(c & 3) * 128;   // hi only
        const char* gb = (const char*)Bgl + (size_t)c * 128;         // hi then lo
        uint32_t sa = sb + s * 32768;
        uint32_t sbm = sa + 16384;
        #pragma unroll
        for (int k = 0; k < 4; k++) {
            int r = lr + 32 * k;
            uint32_t off = r * 128 + ((lj ^ (r & 7)) << 4);
            cp_async16(sa + off,  ga + (size_t)r * (PACKW * 2) + lj * 16);
            cp_async16(sbm + off, gb + (size_t)r * (PACKW * 2) + lj * 16);
        }
    };

    float acc[2][8][4];
    #pragma unroll
    for (int ia = 0; ia < 2; ia++)
        #pragma unroll
        for (int j = 0; j < 8; j++)
            #pragma unroll
            for (int q = 0; q < 4; q++) acc[ia][j][q] = 0.f;

    const int arow_lo = (lane & 7) + ((lane >> 3) & 1) * 8;
    const int a_cc_add = (lane >> 4);
    const int brow_lo = (lane & 7) + ((lane >> 4) ? 8 : 0);
    const int b_cc_add = ((lane >> 3) & 1);

    load_chunk_async(0, 0); CP_COMMIT();
    load_chunk_async(1, 1); CP_COMMIT();

    for (int c = 0; c < NCHUNK_C; c++) {
        if (c + 1 < NCHUNK_C) { CP_WAIT(1); } else { CP_WAIT(0); }
        __syncthreads();
        if (c + 2 < NCHUNK_C) { load_chunk_async(c + 2, (c + 2) % 3); CP_COMMIT(); }

        const uint32_t abase = sb + (c % 3) * 32768;
        const uint32_t bbase = abase + 16384;

        #pragma unroll
        for (int ks = 0; ks < 4; ks++) {
            uint32_t af[2][4], bf[8][2];
            #pragma unroll
            for (int ia = 0; ia < 2; ia++) {
                int row = wm * 32 + ia * 16 + arow_lo;
                uint32_t cc = 2 * ks + a_cc_add;
                uint32_t addr = abase + row * 128 + ((cc << 4) ^ ((row & 7) << 4));
                ldsm4(af[ia][0], af[ia][1], af[ia][2], af[ia][3], addr);
            }
            #pragma unroll
            for (int L = 0; L < 4; L++) {
                int row = wn * 64 + L * 16 + brow_lo;
                uint32_t cc = 2 * ks + b_cc_add;
                uint32_t addr = bbase + row * 128 + ((cc << 4) ^ ((row & 7) << 4));
                ldsm4(bf[2 * L][0], bf[2 * L][1], bf[2 * L + 1][0], bf[2 * L + 1][1], addr);
            }
            #pragma unroll
            for (int ia = 0; ia < 2; ia++)
                #pragma unroll
                for (int j = 0; j < 8; j++)
                    mma16816(acc[ia][j], af[ia], bf[j]);
        }
    }

    float*    Cb = C   + (size_t)b * NN * NN;
    uint16_t* Kb = K16 + (size_t)b * NN * NN;
    const int g = lane >> 2, q = lane & 3;
    #pragma unroll
    for (int ia = 0; ia < 2; ia++) {
        int row = m0 + wm * 32 + ia * 16 + g;
        #pragma unroll
        for (int j = 0; j < 8; j++) {
            int col = n0 + wn * 64 + j * 8 + q * 2;
            float a0 = acc[ia][j][0], a1 = acc[ia][j][1];
            float a2 = acc[ia][j][2], a3 = acc[ia][j][3];
            *(float2*)&Cb[(size_t)row * NN + col]       = make_float2(a0, a1);
            *(float2*)&Cb[(size_t)(row + 8) * NN + col] = make_float2(a2, a3);
            uint32_t k0 = key16_of(a0), k1 = key16_of(a1);
            uint32_t k2 = key16_of(a2), k3 = key16_of(a3);
            *(uint32_t*)&Kb[(size_t)row * NN + col]       = k0 | (k1 << 16);
            *(uint32_t*)&Kb[(size_t)(row + 8) * NN + col] = k2 | (k3 << 16);
            if (bx != by) {
                Kb[(size_t)col * NN + row]             = (uint16_t)k0;
                Kb[(size_t)(col + 1) * NN + row]       = (uint16_t)k1;
                Kb[(size_t)col * NN + row + 8]         = (uint16_t)k2;
                Kb[(size_t)(col + 1) * NN + row + 8]   = (uint16_t)k3;
            }
        }
    }
}

// ---------------- 5) topk via u16 screen + exact refetch + fused output ----------------
__global__ void __launch_bounds__(256) topk_out_kernel(float* __restrict__ out)
{
    const int n = blockIdx.x;
    const int b = blockIdx.y;
    const int t = threadIdx.x;

    __shared__ int      hist[256];
    __shared__ unsigned sh_prefix;
    __shared__ int      sh_krem;
    __shared__ int      sh_b1;
    __shared__ float    red_f[8];
    __shared__ int      cand_idx[CAP];
    __shared__ unsigned cand_key[CAP];
    __shared__ int      sel_idx[KTOP];
    __shared__ unsigned sel_key[KTOP];
    __shared__ float    sel_w[KTOP];
    __shared__ int      eq_idx[128];
    __shared__ int      cnt_cand, cnt_gt, cnt_eq;
    __shared__ float    Zsh;

    const uint16_t* krow = g_key16 + ((size_t)b * NN + n) * NN;
    uint32_t kk[8];
    *(uint4*)&kk[0] = ((const uint4*)krow)[2 * t];
    *(uint4*)&kk[4] = ((const uint4*)krow)[2 * t + 1];
    // u16 key j (j=0..15) = (kk[j>>1] >> ((j&1)*16)) & 0xFFFF ; column index = 16*t + j

    if (t == 0) { cnt_cand = 0; cnt_gt = 0; cnt_eq = 0; }
    hist[t] = 0;
    __syncthreads();

    // ---- pass 1: high byte of u16 ----
    #pragma unroll
    for (int j = 0; j < 16; j++) {
        unsigned k = (kk[j >> 1] >> ((j & 1) * 16)) & 0xFFFFu;
        atomicAdd(&hist[k >> 8], 1);
    }
    __syncthreads();
    if (t < 32) {
        int bins[8], local = 0;
        #pragma unroll
        for (int i2 = 0; i2 < 8; i2++) { bins[i2] = hist[255 - 8 * t - i2]; local += bins[i2]; }
        int excl = local;
        #pragma unroll
        for (int o = 1; o < 32; o <<= 1) {
            int v = __shfl_up_sync(0xffffffffu, excl, o);
            if (t >= o) excl += v;
        }
        excl -= local;
        if (excl < KTOP && KTOP <= excl + local) {
            int run = excl, digit = 0;
            #pragma unroll
            for (int i2 = 0; i2 < 8; i2++) {
                if (run + bins[i2] >= KTOP) { digit = 255 - 8 * t - i2; break; }
                run += bins[i2];
            }
            sh_b1 = digit;
            sh_krem = KTOP - run;
        }
    }
    __syncthreads();
    const int b1 = sh_b1;
    const int krem1 = sh_krem;
    hist[t] = 0;
    __syncthreads();

    // ---- pass 2: low byte among keys with high byte == b1 ----
    #pragma unroll
    for (int j = 0; j < 16; j++) {
        unsigned k = (kk[j >> 1] >> ((j & 1) * 16)) & 0xFFFFu;
        if ((int)(k >> 8) == b1) atomicAdd(&hist[k & 0xFF], 1);
    }
    __syncthreads();
    if (t < 32) {
        int bins[8], local = 0;
        #pragma unroll
        for (int i2 = 0; i2 < 8; i2++) { bins[i2] = hist[255 - 8 * t - i2]; local += bins[i2]; }
        int excl = local;
        #pragma unroll
        for (int o = 1; o < 32; o <<= 1) {
            int v = __shfl_up_sync(0xffffffffu, excl, o);
            if (t >= o) excl += v;
        }
        excl -= local;
        if (excl < krem1 && krem1 <= excl + local) {
            int run = excl, digit = 0;
            #pragma unroll
            for (int i2 = 0; i2 < 8; i2++) {
                if (run + bins[i2] >= krem1) { digit = 255 - 8 * t - i2; break; }
                run += bins[i2];
            }
            sh_b1 = (b1 << 8) | digit;   // reuse sh_b1 to carry T16
        }
    }
    __syncthreads();
    const unsigned T16 = (unsigned)sh_b1;

    // ---- candidate collection (all keys >= T16; superset of exact top-64) ----
    #pragma unroll
    for (int j = 0; j < 16; j++) {
        unsigned k = (kk[j >> 1] >> ((j & 1) * 16)) & 0xFFFFu;
        if (k >= T16) {
            int p = atomicAdd(&cnt_cand, 1);
            if (p < CAP) cand_idx[p] = 16 * t + j;
        }
    }
    __syncthreads();
    const int ncand = cnt_cand;
    const float* cosb = g_cos + (size_t)b * NN * NN;
    const int tr = n >> 7;

    if (ncand <= CAP) {
        // exact values for candidates (triangle-aware)
        for (int s = t; s < ncand; s += 256) {
            int c = cand_idx[s];
            size_t a = ((c >> 7) <= tr) ? ((size_t)n * NN + c) : ((size_t)c * NN + n);
            cand_key[s] = key32_of_bits(__float_as_uint(__ldg(&cosb[a])));
        }
        if (t == 0) { sh_prefix = 0u; sh_krem = KTOP; }
        __syncthreads();

        // exact 4-pass radix over candidates
        #pragma unroll
        for (int d = 3; d >= 0; d--) {
            hist[t] = 0;
            __syncthreads();
            const unsigned prefix = sh_prefix;
            const int krem = sh_krem;
            const int shift = d * 8;
            const unsigned mask = (d == 3) ? 0u : (0xFFFFFFFFu << (8 * (d + 1)));
            for (int s = t; s < ncand; s += 256) {
                unsigned u = cand_key[s];
                if ((u & mask) == prefix) atomicAdd(&hist[(u >> shift) & 0xFF], 1);
            }
            __syncthreads();
            if (t < 32) {
                int bins[8], local = 0;
                #pragma unroll
                for (int i2 = 0; i2 < 8; i2++) { bins[i2] = hist[255 - 8 * t - i2]; local += bins[i2]; }
                int excl = local;
                #pragma unroll
                for (int o = 1; o < 32; o <<= 1) {
                    int v = __shfl_up_sync(0xffffffffu, excl, o);
                    if (t >= o) excl += v;
                }
                excl -= local;
                if (excl < krem && krem <= excl + local) {
                    int run = excl, digit = 0, gt_before = excl;
                    #pragma unroll
                    for (int i2 = 0; i2 < 8; i2++) {
                        if (run + bins[i2] >= krem) { digit = 255 - 8 * t - i2; gt_before = run; break; }
                        run += bins[i2];
                    }
                    sh_prefix = prefix | ((unsigned)digit << shift);
                    sh_krem = krem - gt_before;
                }
            }
            __syncthreads();
        }
        const unsigned ustar = sh_prefix;
        for (int s = t; s < ncand; s += 256) {
            unsigned u = cand_key[s];
            if (u > ustar) {
                int p = atomicAdd(&cnt_gt, 1);
                sel_idx[p] = cand_idx[s];
                sel_key[p] = u;
            } else if (u == ustar) {
                int p = atomicAdd(&cnt_eq, 1);
                if (p < 128) eq_idx[p] = cand_idx[s];
            }
        }
        __syncthreads();
    } else {
        // ---- fallback: full-row exact (statistically never taken) ----
        unsigned kreg[16];
        #pragma unroll
        for (int j = 0; j < 16; j++) {
            int c = 16 * t + j;
            size_t a = ((c >> 7) <= tr) ? ((size_t)n * NN + c) : ((size_t)c * NN + n);
            kreg[j] = key32_of_bits(__float_as_uint(cosb[a]));
        }
        if (t == 0) { sh_prefix = 0u; sh_krem = KTOP; }
        __syncthreads();
        #pragma unroll
        for (int d = 3; d >= 0; d--) {
            hist[t] = 0;
            __syncthreads();
            const unsigned prefix = sh_prefix;
            const int krem = sh_krem;
            const int shift = d * 8;
            const unsigned mask = (d == 3) ? 0u : (0xFFFFFFFFu << (8 * (d + 1)));
            #pragma unroll
            for (int j = 0; j < 16; j++) {
                unsigned u = kreg[j];
                if ((u & mask) == prefix) atomicAdd(&hist[(u >> shift) & 0xFF], 1);
            }
            __syncthreads();
            if (t < 32) {
                int bins[8], local = 0;
                #pragma unroll
                for (int i2 = 0; i2 < 8; i2++) { bins[i2] = hist[255 - 8 * t - i2]; local += bins[i2]; }
                int excl = local;
                #pragma unroll
                for (int o = 1; o < 32; o <<= 1) {
                    int v = __shfl_up_sync(0xffffffffu, excl, o);
                    if (t >= o) excl += v;
                }
                excl -= local;
                if (excl < krem && krem <= excl + local) {
                    int run = excl, digit = 0, gt_before = excl;
                    #pragma unroll
                    for (int i2 = 0; i2 < 8; i2++) {
                        if (run + bins[i2] >= krem) { digit = 255 - 8 * t - i2; gt_before = run; break; }
                        run += bins[i2];
                    }
                    sh_prefix = prefix | ((unsigned)digit << shift);
                    sh_krem = krem - gt_before;
                }
            }
            __syncthreads();
        }
        const unsigned ustar = sh_prefix;
        #pragma unroll
        for (int j = 0; j < 16; j++) {
            unsigned u = kreg[j];
            if (u > ustar) {
                int p = atomicAdd(&cnt_gt, 1);
                sel_idx[p] = 16 * t + j;
                sel_key[p] = u;
            } else if (u == ustar) {
                int p = atomicAdd(&cnt_eq, 1);
                if (p < 128) eq_idx[p] = 16 * t + j;
            }
        }
        __syncthreads();
    }

    // ---- common tail: stable ties, weights, Z, gather, out ----
    const int r = sh_krem;
    const unsigned ustar = sh_prefix;
    const int ngt = cnt_gt;
    if (t == 0) {
        int ne = cnt_eq < 128 ? cnt_eq : 128;
        for (int a = 1; a < ne; a++) {
            int v = eq_idx[a]; int c2 = a - 1;
            while (c2 >= 0 && eq_idx[c2] > v) { eq_idx[c2 + 1] = eq_idx[c2]; c2--; }
            eq_idx[c2 + 1] = v;
        }
        for (int a = 0; a < r; a++) { sel_idx[ngt + a] = eq_idx[a]; sel_key[ngt + a] = ustar; }
    }
    __syncthreads();

    float e_val = 0.f;
    if (t < KTOP) {
        unsigned u = sel_key[t];
        float v = (u & 0x80000000u) ? __uint_as_float(u & 0x7FFFFFFFu) : __uint_as_float(~u);
        e_val = expf(v);
        sel_w[t] = e_val - 1.0f;
    }
    float s = e_val;
    #pragma unroll
    for (int o = 16; o; o >>= 1) s += __shfl_xor_sync(0xffffffffu, s, o);
    if ((t & 31) == 0) red_f[t >> 5] = s;
    __syncthreads();
    if (t == 0) {
        float z = (float)(NN - KTOP);
        #pragma unroll
        for (int w = 0; w < 8; w++) z += red_f[w];
        Zsh = z;
    }
    __syncthreads();

    const __nv_bfloat16* Vb = g_value + (size_t)b * NN * DD;
    float acc = g_sumv[b * DD + t];
    const float invZ = 1.0f / Zsh;
    #pragma unroll 8
    for (int k = 0; k < KTOP; k++)
        acc += sel_w[k] * __bfloat162float(Vb[(size_t)sel_idx[k] * DD + t]);
    out[((size_t)b * NN + n) * DD + t] = acc * invZ;
}

// ---------------- launch ----------------
extern "C" void kernel_launch(void* const* d_in, const int* in_sizes, int n_in,
                              void* d_out, int out_size)
{
    const float* x    = (const float*)d_in[0];
    const float* W    = (const float*)d_in[1];
    const float* bias = (const float*)d_in[2];
    float*       out  = (float*)d_out;

    float* p_cos;
    uint16_t* p_key;
    cudaGetSymbolAddress((void**)&p_cos, g_cos);
    cudaGetSymbolAddress((void**)&p_key, g_key16);

    const int MMA_SMEM = 3 * 32768;
    cudaFuncSetAttribute(cosmma_kernel,   cudaFuncAttributeMaxDynamicSharedMemorySize, MMA_SMEM);
    cudaFuncSetAttribute(valuemma_kernel, cudaFuncAttributeMaxDynamicSharedMemorySize, MMA_SMEM);

    normalize_pack_kernel<<<BB * NN, DD>>>(x, W);                                   // #1
    xsum_part_kernel<<<dim3(16, BB), DD>>>(x);                                      // #2
    valuemma_kernel<<<dim3(DD / 128, (BB * NN) / 128), 256, MMA_SMEM>>>(bias);      // #3
    cosmma_kernel<<<dim3((NN / 128) * (NN / 128 + 1) / 2, 1, BB), 256, MMA_SMEM>>>(p_cos, p_key);  // #4 (profiler)
    sumv_mv_kernel<<<BB, DD>>>(W, bias);                                            // #5
    topk_out_kernel<<<dim3(NN, BB), 256>>>(out);                                    // #6
}

// round 12
// speedup vs baseline: 1.1248x; 1.1248x over previous
#include <cuda_runtime.h>
#include <cuda_bf16.h>
#include <cstdint>
#include <math.h>

#define BB 4
#define NN 4096
#define DD 256
#define KTOP 64
#define EPSN 1e-12f

#define PACKW 512             // [hi(256) | lo(256)] per row
#define NCHUNK_V 12           // value: full 3-term split
#define NCHUNK_C 8            // cos: H·(H+L)^T

// ---------------- scratch ----------------
__device__ __nv_bfloat16  g_value[(size_t)BB * NN * DD];
__device__ float          g_cos  [(size_t)BB * NN * NN];
__device__ __nv_bfloat16  g_pack [(size_t)BB * NN * PACKW];
__device__ __nv_bfloat16  g_Wpack[(size_t)DD * PACKW];
__device__ float          g_norm [(size_t)BB * NN];
__device__ float          g_xsum_part[BB * 16 * DD];
__device__ float          g_sumv[BB * DD];

__device__ __constant__ int CAMAP_V[NCHUNK_V] = {0,1,2,3, 0,1,2,3, 4,5,6,7};
__device__ __constant__ int CBMAP_V[NCHUNK_V] = {0,1,2,3, 4,5,6,7, 0,1,2,3};

__device__ __forceinline__ uint32_t smem_to_u32(const void* p) {
    uint32_t a;
    asm("{ .reg .u64 t; cvta.to.shared.u64 t, %1; cvt.u32.u64 %0, t; }" : "=r"(a) : "l"(p));
    return a;
}
__device__ __forceinline__ void ldsm4(uint32_t& r0, uint32_t& r1, uint32_t& r2, uint32_t& r3, uint32_t addr) {
    asm volatile("ldmatrix.sync.aligned.m8n8.x4.shared.b16 {%0,%1,%2,%3}, [%4];"
        : "=r"(r0), "=r"(r1), "=r"(r2), "=r"(r3) : "r"(addr));
}
__device__ __forceinline__ void mma16816(float* d, const uint32_t* a, const uint32_t* b) {
    asm volatile("mma.sync.aligned.m16n8k16.row.col.f32.bf16.bf16.f32 "
        "{%0,%1,%2,%3}, {%4,%5,%6,%7}, {%8,%9}, {%0,%1,%2,%3};"
        : "+f"(d[0]), "+f"(d[1]), "+f"(d[2]), "+f"(d[3])
        : "r"(a[0]), "r"(a[1]), "r"(a[2]), "r"(a[3]), "r"(b[0]), "r"(b[1]));
}
__device__ __forceinline__ void cp_async16(uint32_t saddr, const void* gptr) {
    asm volatile("cp.async.cg.shared.global [%0], [%1], 16;" :: "r"(saddr), "l"(gptr) : "memory");
}
#define CP_COMMIT() asm volatile("cp.async.commit_group;" ::: "memory")
#define CP_WAIT(N)  asm volatile("cp.async.wait_group %0;" :: "n"(N) : "memory")

// ---------------- 1) normalize + hi/lo pack + norm save (+ W pack piggyback) ----------------
__global__ void __launch_bounds__(DD) normalize_pack_kernel(const float* __restrict__ x,
                                                            const float* __restrict__ W)
{
    int row = blockIdx.x;
    int d   = threadIdx.x;
    float v = x[(size_t)row * DD + d];
    float s = v * v;
    __shared__ float red[8];
    #pragma unroll
    for (int o = 16; o; o >>= 1) s += __shfl_xor_sync(0xffffffffu, s, o);
    if ((d & 31) == 0) red[d >> 5] = s;
    __syncthreads();
    if (d < 32) {
        float t = (d < 8) ? red[d] : 0.f;
        #pragma unroll
        for (int o = 4; o; o >>= 1) t += __shfl_xor_sync(0xffffffffu, t, o);
        if (d == 0) red[0] = t;
    }
    __syncthreads();
    float norm = sqrtf(red[0]);
    float nv = v / fmaxf(norm, EPSN);

    __nv_bfloat16 hi = __float2bfloat16(nv);
    __nv_bfloat16 lo = __float2bfloat16(nv - __bfloat162float(hi));

    size_t base = (size_t)row * PACKW;
    g_pack[base + d]       = hi;
    g_pack[base + 256 + d] = lo;
    if (d == 0) g_norm[row] = norm;

    if (row < DD) {
        float w = W[(size_t)row * DD + d];
        __nv_bfloat16 whi = __float2bfloat16(w);
        __nv_bfloat16 wlo = __float2bfloat16(w - __bfloat162float(whi));
        g_Wpack[(size_t)row * PACKW + d]       = whi;
        g_Wpack[(size_t)row * PACKW + 256 + d] = wlo;
    }
}

// ---------------- 1b) per-batch partial column sums of x ----------------
__global__ void __launch_bounds__(DD) xsum_part_kernel(const float* __restrict__ x)
{
    int b = blockIdx.y, c = blockIdx.x, e = threadIdx.x;
    const float* base = x + (size_t)b * NN * DD + (size_t)c * 256 * DD + e;
    float s = 0.f;
    #pragma unroll 8
    for (int n = 0; n < 256; n++) s += base[(size_t)n * DD];
    g_xsum_part[(b * 16 + c) * DD + e] = s;
}

// ---------------- 1c) sumv = (colsum x) @ W^T + N*b  (exact algebra) ----------------
__global__ void __launch_bounds__(DD) sumv_mv_kernel(const float* __restrict__ W,
                                                     const float* __restrict__ bias)
{
    int b = blockIdx.x, t = threadIdx.x;
    __shared__ float xs[DD];
    float s = 0.f;
    #pragma unroll
    for (int c = 0; c < 16; c++) s += g_xsum_part[(b * 16 + c) * DD + t];
    xs[t] = s;
    __syncthreads();
    float acc = 0.f;
    const float4* Wr = (const float4*)&W[(size_t)t * DD];
    #pragma unroll 8
    for (int d4 = 0; d4 < 64; d4++) {
        float4 w = Wr[d4];
        acc += xs[d4 * 4 + 0] * w.x + xs[d4 * 4 + 1] * w.y
             + xs[d4 * 4 + 2] * w.z + xs[d4 * 4 + 3] * w.w;
    }
    g_sumv[b * DD + t] = acc + (float)NN * bias[t];
}

// ---------------- 2) value = norm * (nx @ W^T) + b  -> bf16 ----------------
__global__ void __launch_bounds__(256, 2) valuemma_kernel(const float* __restrict__ bias)
{
    extern __shared__ char smem[];
    const uint32_t sb = smem_to_u32(smem);

    const int tid  = threadIdx.x;
    const int wid  = tid >> 5;
    const int lane = tid & 31;
    const int wm   = wid & 3;
    const int wn   = wid >> 2;
    const int m0   = blockIdx.y * 128;
    const int n0   = blockIdx.x * 128;

    const __nv_bfloat16* Agl = g_pack  + (size_t)m0 * PACKW;
    const __nv_bfloat16* Bgl = g_Wpack + (size_t)n0 * PACKW;

    const int lr = tid >> 3;
    const int lj = tid & 7;

    auto load_chunk_async = [&](int c, int s) {
        const char* ga = (const char*)Agl + (size_t)CAMAP_V[c] * 128;
        const char* gb = (const char*)Bgl + (size_t)CBMAP_V[c] * 128;
        uint32_t sa = sb + s * 32768;
        uint32_t sbm = sa + 16384;
        #pragma unroll
        for (int k = 0; k < 4; k++) {
            int r = lr + 32 * k;
            uint32_t off = r * 128 + ((lj ^ (r & 7)) << 4);
            cp_async16(sa + off,  ga + (size_t)r * (PACKW * 2) + lj * 16);
            cp_async16(sbm + off, gb + (size_t)r * (PACKW * 2) + lj * 16);
        }
    };

    float acc[2][8][4];
    #pragma unroll
    for (int ia = 0; ia < 2; ia++)
        #pragma unroll
        for (int j = 0; j < 8; j++)
            #pragma unroll
            for (int q = 0; q < 4; q++) acc[ia][j][q] = 0.f;

    const int arow_lo = (lane & 7) + ((lane >> 3) & 1) * 8;
    const int a_cc_add = (lane >> 4);
    const int brow_lo = (lane & 7) + ((lane >> 4) ? 8 : 0);
    const int b_cc_add = ((lane >> 3) & 1);

    load_chunk_async(0, 0); CP_COMMIT();
    load_chunk_async(1, 1); CP_COMMIT();

    for (int c = 0; c < NCHUNK_V; c++) {
        if (c + 1 < NCHUNK_V) { CP_WAIT(1); } else { CP_WAIT(0); }
        __syncthreads();
        if (c + 2 < NCHUNK_V) { load_chunk_async(c + 2, (c + 2) % 3); CP_COMMIT(); }

        const uint32_t abase = sb + (c % 3) * 32768;
        const uint32_t bbase = abase + 16384;

        #pragma unroll
        for (int ks = 0; ks < 4; ks++) {
            uint32_t af[2][4], bf[8][2];
            #pragma unroll
            for (int ia = 0; ia < 2; ia++) {
                int row = wm * 32 + ia * 16 + arow_lo;
                uint32_t cc = 2 * ks + a_cc_add;
                uint32_t addr = abase + row * 128 + ((cc << 4) ^ ((row & 7) << 4));
                ldsm4(af[ia][0], af[ia][1], af[ia][2], af[ia][3], addr);
            }
            #pragma unroll
            for (int L = 0; L < 4; L++) {
                int row = wn * 64 + L * 16 + brow_lo;
                uint32_t cc = 2 * ks + b_cc_add;
                uint32_t addr = bbase + row * 128 + ((cc << 4) ^ ((row & 7) << 4));
                ldsm4(bf[2 * L][0], bf[2 * L][1], bf[2 * L + 1][0], bf[2 * L + 1][1], addr);
            }
            #pragma unroll
            for (int ia = 0; ia < 2; ia++)
                #pragma unroll
                for (int j = 0; j < 8; j++)
                    mma16816(acc[ia][j], af[ia], bf[j]);
        }
    }

    const int g = lane >> 2, q = lane & 3;
    #pragma unroll
    for (int ia = 0; ia < 2; ia++) {
        int row = m0 + wm * 32 + ia * 16 + g;
        float nr0 = __ldg(&g_norm[row]);
        float nr8 = __ldg(&g_norm[row + 8]);
        #pragma unroll
        for (int j = 0; j < 8; j++) {
            int col = n0 + wn * 64 + j * 8 + q * 2;
            float b0 = __ldg(&bias[col]), b1 = __ldg(&bias[col + 1]);
            __nv_bfloat162 v01 = __floats2bfloat162_rn(acc[ia][j][0] * nr0 + b0, acc[ia][j][1] * nr0 + b1);
            __nv_bfloat162 v23 = __floats2bfloat162_rn(acc[ia][j][2] * nr8 + b0, acc[ia][j][3] * nr8 + b1);
            *(__nv_bfloat162*)&g_value[(size_t)row * DD + col]       = v01;
            *(__nv_bfloat162*)&g_value[(size_t)(row + 8) * DD + col] = v23;
        }
    }
}

// ---------------- 4) cos = H @ (H+L)^T  (R8 config: 128x128, 3-stage, direct epilogue) ----------------
__global__ void __launch_bounds__(256, 2) cosmma_kernel(float* __restrict__ C)
{
    extern __shared__ char smem[];
    const uint32_t sb = smem_to_u32(smem);

    const int tid  = threadIdx.x;
    const int wid  = tid >> 5;
    const int lane = tid & 31;
    const int wm   = wid & 3;
    const int wn   = wid >> 2;
    const int b    = blockIdx.z;

    int i  = blockIdx.x;
    int by = (int)((sqrtf(8.f * (float)i + 1.f) - 1.f) * 0.5f);
    while ((by + 1) * (by + 2) / 2 <= i) by++;
    while (by * (by + 1) / 2 > i) by--;
    int bx = i - by * (by + 1) / 2;
    const int m0 = by * 128;
    const int n0 = bx * 128;

    const __nv_bfloat16* Agl = g_pack + ((size_t)b * NN + m0) * PACKW;
    const __nv_bfloat16* Bgl = g_pack + ((size_t)b * NN + n0) * PACKW;

    const int lr = tid >> 3;
    const int lj = tid & 7;

    auto load_chunk_async = [&](int c, int s) {
        const char* ga = (const char*)Agl + (size_t)(c & 3) * 128;   // hi only
        const char* gb = (const char*)Bgl + (size_t)c * 128;         // hi then lo
        uint32_t sa = sb + s * 32768;
        uint32_t sbm = sa + 16384;
        #pragma unroll
        for (int k = 0; k < 4; k++) {
            int r = lr + 32 * k;
            uint32_t off = r * 128 + ((lj ^ (r & 7)) << 4);
            cp_async16(sa + off,  ga + (size_t)r * (PACKW * 2) + lj * 16);
            cp_async16(sbm + off, gb + (size_t)r * (PACKW * 2) + lj * 16);
        }
    };

    float acc[2][8][4];
    #pragma unroll
    for (int ia = 0; ia < 2; ia++)
        #pragma unroll
        for (int j = 0; j < 8; j++)
            #pragma unroll
            for (int q = 0; q < 4; q++) acc[ia][j][q] = 0.f;

    const int arow_lo = (lane & 7) + ((lane >> 3) & 1) * 8;
    const int a_cc_add = (lane >> 4);
    const int brow_lo = (lane & 7) + ((lane >> 4) ? 8 : 0);
    const int b_cc_add = ((lane >> 3) & 1);

    load_chunk_async(0, 0); CP_COMMIT();
    load_chunk_async(1, 1); CP_COMMIT();

    for (int c = 0; c < NCHUNK_C; c++) {
        if (c + 1 < NCHUNK_C) { CP_WAIT(1); } else { CP_WAIT(0); }
        __syncthreads();
        if (c + 2 < NCHUNK_C) { load_chunk_async(c + 2, (c + 2) % 3); CP_COMMIT(); }

        const uint32_t abase = sb + (c % 3) * 32768;
        const uint32_t bbase = abase + 16384;

        #pragma unroll
        for (int ks = 0; ks < 4; ks++) {
            uint32_t af[2][4], bf[8][2];
            #pragma unroll
            for (int ia = 0; ia < 2; ia++) {
                int row = wm * 32 + ia * 16 + arow_lo;
                uint32_t cc = 2 * ks + a_cc_add;
                uint32_t addr = abase + row * 128 + ((cc << 4) ^ ((row & 7) << 4));
                ldsm4(af[ia][0], af[ia][1], af[ia][2], af[ia][3], addr);
            }
            #pragma unroll
            for (int L = 0; L < 4; L++) {
                int row = wn * 64 + L * 16 + brow_lo;
                uint32_t cc = 2 * ks + b_cc_add;
                uint32_t addr = bbase + row * 128 + ((cc << 4) ^ ((row & 7) << 4));
                ldsm4(bf[2 * L][0], bf[2 * L][1], bf[2 * L + 1][0], bf[2 * L + 1][1], addr);
            }
            #pragma unroll
            for (int ia = 0; ia < 2; ia++)
                #pragma unroll
                for (int j = 0; j < 8; j++)
                    mma16816(acc[ia][j], af[ia], bf[j]);
        }
    }

    float* Cb = C + (size_t)b * NN * NN;
    const int g = lane >> 2, q = lane & 3;
    #pragma unroll
    for (int ia = 0; ia < 2; ia++) {
        int row = m0 + wm * 32 + ia * 16 + g;
        #pragma unroll
        for (int j = 0; j < 8; j++) {
            int col = n0 + wn * 64 + j * 8 + q * 2;
            *(float2*)&Cb[(size_t)row * NN + col]       = make_float2(acc[ia][j][0], acc[ia][j][1]);
            *(float2*)&Cb[(size_t)(row + 8) * NN + col] = make_float2(acc[ia][j][2], acc[ia][j][3]);
        }
    }
    if (bx != by) {
        #pragma unroll
        for (int ia = 0; ia < 2; ia++) {
            int row = m0 + wm * 32 + ia * 16 + g;
            #pragma unroll
            for (int j = 0; j < 8; j++) {
                int col = n0 + wn * 64 + j * 8 + q * 2;
                Cb[(size_t)col * NN + row]           = acc[ia][j][0];
                Cb[(size_t)(col + 1) * NN + row]     = acc[ia][j][1];
                Cb[(size_t)col * NN + row + 8]       = acc[ia][j][2];
                Cb[(size_t)(col + 1) * NN + row + 8] = acc[ia][j][3];
            }
        }
    }
}

// ---------------- 5) radix-select top-64 (per-warp hist on pass 1) + fused output ----------------
__global__ void __launch_bounds__(256) topk_out_kernel(float* __restrict__ out)
{
    const int n = blockIdx.x;
    const int b = blockIdx.y;
    const int t = threadIdx.x;
    const int wid = t >> 5;

    __shared__ int      hist8[8][256];      // per-warp histograms (pass 1 only)
    __shared__ int      hist[256];
    __shared__ unsigned sh_prefix;
    __shared__ int      sh_krem;
    __shared__ float    red_f[8];
    __shared__ int      sel_idx[KTOP];
    __shared__ unsigned sel_key[KTOP];
    __shared__ float    sel_w[KTOP];
    __shared__ int      eq_idx[128];
    __shared__ int      cnt_gt, cnt_eq;
    __shared__ float    Zsh;

    const float* row = g_cos + ((size_t)b * NN + n) * NN;

    unsigned kreg[16];
    #pragma unroll
    for (int j = 0; j < 4; j++) {
        float4 v = *(const float4*)&row[1024 * j + 4 * t];
        const float vv[4] = {v.x, v.y, v.z, v.w};
        #pragma unroll
        for (int q = 0; q < 4; q++) {
            unsigned x = __float_as_uint(vv[q]);
            kreg[4 * j + q] = (x & 0x80000000u) ? ~x : (x | 0x80000000u);
        }
    }
    if (t == 0) { cnt_gt = 0; cnt_eq = 0; }
    #pragma unroll
    for (int w = 0; w < 8; w++) hist8[w][t] = 0;
    __syncthreads();

    // ---- pass d=3: per-warp histograms (8x atomic parallelism on hot bins) ----
    #pragma unroll
    for (int j = 0; j < 16; j++) atomicAdd(&hist8[wid][kreg[j] >> 24], 1);
    __syncthreads();
    if (t < 32) {
        int bins[8], local = 0;
        #pragma unroll
        for (int i2 = 0; i2 < 8; i2++) {
            int bin = 255 - 8 * t - i2, s = 0;
            #pragma unroll
            for (int w = 0; w < 8; w++) s += hist8[w][bin];
            bins[i2] = s; local += s;
        }
        int excl = local;
        #pragma unroll
        for (int o = 1; o < 32; o <<= 1) {
            int v = __shfl_up_sync(0xffffffffu, excl, o);
            if (t >= o) excl += v;
        }
        excl -= local;
        if (excl < KTOP && KTOP <= excl + local) {
            int run = excl, digit = 0, gt_before = excl;
            #pragma unroll
            for (int i2 = 0; i2 < 8; i2++) {
                if (run + bins[i2] >= KTOP) { digit = 255 - 8 * t - i2; gt_before = run; break; }
                run += bins[i2];
            }
            sh_prefix = (unsigned)digit << 24;
            sh_krem = KTOP - gt_before;
        }
    }
    __syncthreads();

    // ---- passes d=2..0: few participants, single histogram ----
    #pragma unroll
    for (int d = 2; d >= 0; d--) {
        hist[t] = 0;
        __syncthreads();
        const unsigned prefix = sh_prefix;
        const int krem = sh_krem;
        const int shift = d * 8;
        const unsigned mask = 0xFFFFFFFFu << (8 * (d + 1));
        #pragma unroll
        for (int j = 0; j < 16; j++) {
            unsigned u = kreg[j];
            if ((u & mask) == prefix) atomicAdd(&hist[(u >> shift) & 0xFF], 1);
        }
        __syncthreads();
        if (t < 32) {
            int bins[8], local = 0;
            #pragma unroll
            for (int i2 = 0; i2 < 8; i2++) { bins[i2] = hist[255 - 8 * t - i2]; local += bins[i2]; }
            int excl = local;
            #pragma unroll
            for (int o = 1; o < 32; o <<= 1) {
                int v = __shfl_up_sync(0xffffffffu, excl, o);
                if (t >= o) excl += v;
            }
            excl -= local;
            if (excl < krem && krem <= excl + local) {
                int run = excl, digit = 0, gt_before = excl;
                #pragma unroll
                for (int i2 = 0; i2 < 8; i2++) {
                    if (run + bins[i2] >= krem) { digit = 255 - 8 * t - i2; gt_before = run; break; }
                    run += bins[i2];
                }
                sh_prefix = prefix | ((unsigned)digit << shift);
                sh_krem = krem - gt_before;
            }
        }
        __syncthreads();
    }
    const unsigned ustar = sh_prefix;
    const int r = sh_krem;

    #pragma unroll
    for (int j = 0; j < 16; j++) {
        unsigned u = kreg[j];
        int idx = ((j >> 2) << 10) + (t << 2) + (j & 3);
        if (u > ustar) {
            int p = atomicAdd(&cnt_gt, 1);
            sel_idx[p] = idx;
            sel_key[p] = u;
        } else if (u == ustar) {
            int p = atomicAdd(&cnt_eq, 1);
            if (p < 128) eq_idx[p] = idx;
        }
    }
    __syncthreads();

    const int ngt = cnt_gt;
    if (t == 0) {
        int ne = cnt_eq < 128 ? cnt_eq : 128;
        for (int a = 1; a < ne; a++) {
            int v = eq_idx[a]; int c2 = a - 1;
            while (c2 >= 0 && eq_idx[c2] > v) { eq_idx[c2 + 1] = eq_idx[c2]; c2--; }
            eq_idx[c2 + 1] = v;
        }
        for (int a = 0; a < r; a++) { sel_idx[ngt + a] = eq_idx[a]; sel_key[ngt + a] = ustar; }
    }
    __syncthreads();

    float e_val = 0.f;
    if (t < KTOP) {
        unsigned u = sel_key[t];
        float v = (u & 0x80000000u) ? __uint_as_float(u & 0x7FFFFFFFu) : __uint_as_float(~u);
        e_val = expf(v);
        sel_w[t] = e_val - 1.0f;
    }
    float s = e_val;
    #pragma unroll
    for (int o = 16; o; o >>= 1) s += __shfl_xor_sync(0xffffffffu, s, o);
    if ((t & 31) == 0) red_f[t >> 5] = s;
    __syncthreads();
    if (t == 0) {
        float z = (float)(NN - KTOP);
        #pragma unroll
        for (int w = 0; w < 8; w++) z += red_f[w];
        Zsh = z;
    }
    __syncthreads();

    const __nv_bfloat16* Vb = g_value + (size_t)b * NN * DD;
    float acc = g_sumv[b * DD + t];
    const float invZ = 1.0f / Zsh;
    #pragma unroll 8
    for (int k = 0; k < KTOP; k++)
        acc += sel_w[k] * __bfloat162float(Vb[(size_t)sel_idx[k] * DD + t]);
    out[((size_t)b * NN + n) * DD + t] = acc * invZ;
}

// ---------------- launch ----------------
extern "C" void kernel_launch(void* const* d_in, const int* in_sizes, int n_in,
                              void* d_out, int out_size)
{
    const float* x    = (const float*)d_in[0];
    const float* W    = (const float*)d_in[1];
    const float* bias = (const float*)d_in[2];
    float*       out  = (float*)d_out;

    float* p_cos;
    cudaGetSymbolAddress((void**)&p_cos, g_cos);

    const int MMA_SMEM = 3 * 32768;
    cudaFuncSetAttribute(cosmma_kernel,   cudaFuncAttributeMaxDynamicSharedMemorySize, MMA_SMEM);
    cudaFuncSetAttribute(valuemma_kernel, cudaFuncAttributeMaxDynamicSharedMemorySize, MMA_SMEM);

    normalize_pack_kernel<<<BB * NN, DD>>>(x, W);                                   // #1
    xsum_part_kernel<<<dim3(16, BB), DD>>>(x);                                      // #2
    valuemma_kernel<<<dim3(DD / 128, (BB * NN) / 128), 256, MMA_SMEM>>>(bias);      // #3
    cosmma_kernel<<<dim3((NN / 128) * (NN / 128 + 1) / 2, 1, BB), 256, MMA_SMEM>>>(p_cos);  // #4 (profiler)
    sumv_mv_kernel<<<BB, DD>>>(W, bias);                                            // #5
    topk_out_kernel<<<dim3(NN, BB), 256>>>(out);                                    // #6
}

// round 13
// speedup vs baseline: 1.1820x; 1.0508x over previous
#include <cuda_runtime.h>
#include <cuda_bf16.h>
#include <cstdint>
#include <math.h>

#define BB 4
#define NN 4096
#define DD 256
#define KTOP 64
#define EPSN 1e-12f

#define PACKW 512             // [hi(256) | lo(256)] per row
#define NCHUNK_V 12           // value: full 3-term split
#define NCHUNK_C 8            // cos: H·(H+L)^T

// ---------------- scratch ----------------
__device__ __nv_bfloat16  g_value[(size_t)BB * NN * DD];
__device__ float          g_cos  [(size_t)BB * NN * NN];
__device__ __nv_bfloat16  g_pack [(size_t)BB * NN * PACKW];
__device__ __nv_bfloat16  g_Wpack[(size_t)DD * PACKW];
__device__ float          g_norm [(size_t)BB * NN];
__device__ float          g_xsum_part[BB * 16 * DD];
__device__ float          g_sumv[BB * DD];

__device__ __constant__ int CAMAP_V[NCHUNK_V] = {0,1,2,3, 0,1,2,3, 4,5,6,7};
__device__ __constant__ int CBMAP_V[NCHUNK_V] = {0,1,2,3, 4,5,6,7, 0,1,2,3};

__device__ __forceinline__ uint32_t smem_to_u32(const void* p) {
    uint32_t a;
    asm("{ .reg .u64 t; cvta.to.shared.u64 t, %1; cvt.u32.u64 %0, t; }" : "=r"(a) : "l"(p));
    return a;
}
__device__ __forceinline__ void ldsm4(uint32_t& r0, uint32_t& r1, uint32_t& r2, uint32_t& r3, uint32_t addr) {
    asm volatile("ldmatrix.sync.aligned.m8n8.x4.shared.b16 {%0,%1,%2,%3}, [%4];"
        : "=r"(r0), "=r"(r1), "=r"(r2), "=r"(r3) : "r"(addr));
}
__device__ __forceinline__ void mma16816(float* d, const uint32_t* a, const uint32_t* b) {
    asm volatile("mma.sync.aligned.m16n8k16.row.col.f32.bf16.bf16.f32 "
        "{%0,%1,%2,%3}, {%4,%5,%6,%7}, {%8,%9}, {%0,%1,%2,%3};"
        : "+f"(d[0]), "+f"(d[1]), "+f"(d[2]), "+f"(d[3])
        : "r"(a[0]), "r"(a[1]), "r"(a[2]), "r"(a[3]), "r"(b[0]), "r"(b[1]));
}
__device__ __forceinline__ void cp_async16(uint32_t saddr, const void* gptr) {
    asm volatile("cp.async.cg.shared.global [%0], [%1], 16;" :: "r"(saddr), "l"(gptr) : "memory");
}
#define CP_COMMIT() asm volatile("cp.async.commit_group;" ::: "memory")
#define CP_WAIT(N)  asm volatile("cp.async.wait_group %0;" :: "n"(N) : "memory")

// ---------------- 1) normalize + hi/lo pack + norm save (+ W pack piggyback) ----------------
__global__ void __launch_bounds__(DD) normalize_pack_kernel(const float* __restrict__ x,
                                                            const float* __restrict__ W)
{
    int row = blockIdx.x;
    int d   = threadIdx.x;
    float v = x[(size_t)row * DD + d];
    float s = v * v;
    __shared__ float red[8];
    #pragma unroll
    for (int o = 16; o; o >>= 1) s += __shfl_xor_sync(0xffffffffu, s, o);
    if ((d & 31) == 0) red[d >> 5] = s;
    __syncthreads();
    if (d < 32) {
        float t = (d < 8) ? red[d] : 0.f;
        #pragma unroll
        for (int o = 4; o; o >>= 1) t += __shfl_xor_sync(0xffffffffu, t, o);
        if (d == 0) red[0] = t;
    }
    __syncthreads();
    float norm = sqrtf(red[0]);
    float nv = v / fmaxf(norm, EPSN);

    __nv_bfloat16 hi = __float2bfloat16(nv);
    __nv_bfloat16 lo = __float2bfloat16(nv - __bfloat162float(hi));

    size_t base = (size_t)row * PACKW;
    g_pack[base + d]       = hi;
    g_pack[base + 256 + d] = lo;
    if (d == 0) g_norm[row] = norm;

    if (row < DD) {
        float w = W[(size_t)row * DD + d];
        __nv_bfloat16 whi = __float2bfloat16(w);
        __nv_bfloat16 wlo = __float2bfloat16(w - __bfloat162float(whi));
        g_Wpack[(size_t)row * PACKW + d]       = whi;
        g_Wpack[(size_t)row * PACKW + 256 + d] = wlo;
    }
}

// ---------------- 1b) per-batch partial column sums of x ----------------
__global__ void __launch_bounds__(DD) xsum_part_kernel(const float* __restrict__ x)
{
    int b = blockIdx.y, c = blockIdx.x, e = threadIdx.x;
    const float* base = x + (size_t)b * NN * DD + (size_t)c * 256 * DD + e;
    float s = 0.f;
    #pragma unroll 8
    for (int n = 0; n < 256; n++) s += base[(size_t)n * DD];
    g_xsum_part[(b * 16 + c) * DD + e] = s;
}

// ---------------- 1c) sumv = (colsum x) @ W^T + N*b  (exact algebra) ----------------
__global__ void __launch_bounds__(DD) sumv_mv_kernel(const float* __restrict__ W,
                                                     const float* __restrict__ bias)
{
    int b = blockIdx.x, t = threadIdx.x;
    __shared__ float xs[DD];
    float s = 0.f;
    #pragma unroll
    for (int c = 0; c < 16; c++) s += g_xsum_part[(b * 16 + c) * DD + t];
    xs[t] = s;
    __syncthreads();
    float acc = 0.f;
    const float4* Wr = (const float4*)&W[(size_t)t * DD];
    #pragma unroll 8
    for (int d4 = 0; d4 < 64; d4++) {
        float4 w = Wr[d4];
        acc += xs[d4 * 4 + 0] * w.x + xs[d4 * 4 + 1] * w.y
             + xs[d4 * 4 + 2] * w.z + xs[d4 * 4 + 3] * w.w;
    }
    g_sumv[b * DD + t] = acc + (float)NN * bias[t];
}

// ---------------- 2) value = norm * (nx @ W^T) + b  -> bf16 ----------------
__global__ void __launch_bounds__(256, 2) valuemma_kernel(const float* __restrict__ bias)
{
    extern __shared__ char smem[];
    const uint32_t sb = smem_to_u32(smem);

    const int tid  = threadIdx.x;
    const int wid  = tid >> 5;
    const int lane = tid & 31;
    const int wm   = wid & 3;
    const int wn   = wid >> 2;
    const int m0   = blockIdx.y * 128;
    const int n0   = blockIdx.x * 128;

    const __nv_bfloat16* Agl = g_pack  + (size_t)m0 * PACKW;
    const __nv_bfloat16* Bgl = g_Wpack + (size_t)n0 * PACKW;

    const int lr = tid >> 3;
    const int lj = tid & 7;

    auto load_chunk_async = [&](int c, int s) {
        const char* ga = (const char*)Agl + (size_t)CAMAP_V[c] * 128;
        const char* gb = (const char*)Bgl + (size_t)CBMAP_V[c] * 128;
        uint32_t sa = sb + s * 32768;
        uint32_t sbm = sa + 16384;
        #pragma unroll
        for (int k = 0; k < 4; k++) {
            int r = lr + 32 * k;
            uint32_t off = r * 128 + ((lj ^ (r & 7)) << 4);
            cp_async16(sa + off,  ga + (size_t)r * (PACKW * 2) + lj * 16);
            cp_async16(sbm + off, gb + (size_t)r * (PACKW * 2) + lj * 16);
        }
    };

    float acc[2][8][4];
    #pragma unroll
    for (int ia = 0; ia < 2; ia++)
        #pragma unroll
        for (int j = 0; j < 8; j++)
            #pragma unroll
            for (int q = 0; q < 4; q++) acc[ia][j][q] = 0.f;

    const int arow_lo = (lane & 7) + ((lane >> 3) & 1) * 8;
    const int a_cc_add = (lane >> 4);
    const int brow_lo = (lane & 7) + ((lane >> 4) ? 8 : 0);
    const int b_cc_add = ((lane >> 3) & 1);

    load_chunk_async(0, 0); CP_COMMIT();
    load_chunk_async(1, 1); CP_COMMIT();

    for (int c = 0; c < NCHUNK_V; c++) {
        if (c + 1 < NCHUNK_V) { CP_WAIT(1); } else { CP_WAIT(0); }
        __syncthreads();
        if (c + 2 < NCHUNK_V) { load_chunk_async(c + 2, (c + 2) % 3); CP_COMMIT(); }

        const uint32_t abase = sb + (c % 3) * 32768;
        const uint32_t bbase = abase + 16384;

        #pragma unroll
        for (int ks = 0; ks < 4; ks++) {
            uint32_t af[2][4], bf[8][2];
            #pragma unroll
            for (int ia = 0; ia < 2; ia++) {
                int row = wm * 32 + ia * 16 + arow_lo;
                uint32_t cc = 2 * ks + a_cc_add;
                uint32_t addr = abase + row * 128 + ((cc << 4) ^ ((row & 7) << 4));
                ldsm4(af[ia][0], af[ia][1], af[ia][2], af[ia][3], addr);
            }
            #pragma unroll
            for (int L = 0; L < 4; L++) {
                int row = wn * 64 + L * 16 + brow_lo;
                uint32_t cc = 2 * ks + b_cc_add;
                uint32_t addr = bbase + row * 128 + ((cc << 4) ^ ((row & 7) << 4));
                ldsm4(bf[2 * L][0], bf[2 * L][1], bf[2 * L + 1][0], bf[2 * L + 1][1], addr);
            }
            #pragma unroll
            for (int ia = 0; ia < 2; ia++)
                #pragma unroll
                for (int j = 0; j < 8; j++)
                    mma16816(acc[ia][j], af[ia], bf[j]);
        }
    }

    const int g = lane >> 2, q = lane & 3;
    #pragma unroll
    for (int ia = 0; ia < 2; ia++) {
        int row = m0 + wm * 32 + ia * 16 + g;
        float nr0 = __ldg(&g_norm[row]);
        float nr8 = __ldg(&g_norm[row + 8]);
        #pragma unroll
        for (int j = 0; j < 8; j++) {
            int col = n0 + wn * 64 + j * 8 + q * 2;
            float b0 = __ldg(&bias[col]), b1 = __ldg(&bias[col + 1]);
            __nv_bfloat162 v01 = __floats2bfloat162_rn(acc[ia][j][0] * nr0 + b0, acc[ia][j][1] * nr0 + b1);
            __nv_bfloat162 v23 = __floats2bfloat162_rn(acc[ia][j][2] * nr8 + b0, acc[ia][j][3] * nr8 + b1);
            *(__nv_bfloat162*)&g_value[(size_t)row * DD + col]       = v01;
            *(__nv_bfloat162*)&g_value[(size_t)(row + 8) * DD + col] = v23;
        }
    }
}

// ---------------- 4) cos = H @ (H+L)^T  (R8 config: 128x128, 3-stage, direct epilogue) ----------------
__global__ void __launch_bounds__(256, 2) cosmma_kernel(float* __restrict__ C)
{
    extern __shared__ char smem[];
    const uint32_t sb = smem_to_u32(smem);

    const int tid  = threadIdx.x;
    const int wid  = tid >> 5;
    const int lane = tid & 31;
    const int wm   = wid & 3;
    const int wn   = wid >> 2;
    const int b    = blockIdx.z;

    int i  = blockIdx.x;
    int by = (int)((sqrtf(8.f * (float)i + 1.f) - 1.f) * 0.5f);
    while ((by + 1) * (by + 2) / 2 <= i) by++;
    while (by * (by + 1) / 2 > i) by--;
    int bx = i - by * (by + 1) / 2;
    const int m0 = by * 128;
    const int n0 = bx * 128;

    const __nv_bfloat16* Agl = g_pack + ((size_t)b * NN + m0) * PACKW;
    const __nv_bfloat16* Bgl = g_pack + ((size_t)b * NN + n0) * PACKW;

    const int lr = tid >> 3;
    const int lj = tid & 7;

    auto load_chunk_async = [&](int c, int s) {
        const char* ga = (const char*)Agl + (size_t)(c & 3) * 128;   // hi only
        const char* gb = (const char*)Bgl + (size_t)c * 128;         // hi then lo
        uint32_t sa = sb + s * 32768;
        uint32_t sbm = sa + 16384;
        #pragma unroll
        for (int k = 0; k < 4; k++) {
            int r = lr + 32 * k;
            uint32_t off = r * 128 + ((lj ^ (r & 7)) << 4);
            cp_async16(sa + off,  ga + (size_t)r * (PACKW * 2) + lj * 16);
            cp_async16(sbm + off, gb + (size_t)r * (PACKW * 2) + lj * 16);
        }
    };

    float acc[2][8][4];
    #pragma unroll
    for (int ia = 0; ia < 2; ia++)
        #pragma unroll
        for (int j = 0; j < 8; j++)
            #pragma unroll
            for (int q = 0; q < 4; q++) acc[ia][j][q] = 0.f;

    const int arow_lo = (lane & 7) + ((lane >> 3) & 1) * 8;
    const int a_cc_add = (lane >> 4);
    const int brow_lo = (lane & 7) + ((lane >> 4) ? 8 : 0);
    const int b_cc_add = ((lane >> 3) & 1);

    load_chunk_async(0, 0); CP_COMMIT();
    load_chunk_async(1, 1); CP_COMMIT();

    for (int c = 0; c < NCHUNK_C; c++) {
        if (c + 1 < NCHUNK_C) { CP_WAIT(1); } else { CP_WAIT(0); }
        __syncthreads();
        if (c + 2 < NCHUNK_C) { load_chunk_async(c + 2, (c + 2) % 3); CP_COMMIT(); }

        const uint32_t abase = sb + (c % 3) * 32768;
        const uint32_t bbase = abase + 16384;

        #pragma unroll
        for (int ks = 0; ks < 4; ks++) {
            uint32_t af[2][4], bf[8][2];
            #pragma unroll
            for (int ia = 0; ia < 2; ia++) {
                int row = wm * 32 + ia * 16 + arow_lo;
                uint32_t cc = 2 * ks + a_cc_add;
                uint32_t addr = abase + row * 128 + ((cc << 4) ^ ((row & 7) << 4));
                ldsm4(af[ia][0], af[ia][1], af[ia][2], af[ia][3], addr);
            }
            #pragma unroll
            for (int L = 0; L < 4; L++) {
                int row = wn * 64 + L * 16 + brow_lo;
                uint32_t cc = 2 * ks + b_cc_add;
                uint32_t addr = bbase + row * 128 + ((cc << 4) ^ ((row & 7) << 4));
                ldsm4(bf[2 * L][0], bf[2 * L][1], bf[2 * L + 1][0], bf[2 * L + 1][1], addr);
            }
            #pragma unroll
            for (int ia = 0; ia < 2; ia++)
                #pragma unroll
                for (int j = 0; j < 8; j++)
                    mma16816(acc[ia][j], af[ia], bf[j]);
        }
    }

    float* Cb = C + (size_t)b * NN * NN;
    const int g = lane >> 2, q = lane & 3;
    #pragma unroll
    for (int ia = 0; ia < 2; ia++) {
        int row = m0 + wm * 32 + ia * 16 + g;
        #pragma unroll
        for (int j = 0; j < 8; j++) {
            int col = n0 + wn * 64 + j * 8 + q * 2;
            *(float2*)&Cb[(size_t)row * NN + col]       = make_float2(acc[ia][j][0], acc[ia][j][1]);
            *(float2*)&Cb[(size_t)(row + 8) * NN + col] = make_float2(acc[ia][j][2], acc[ia][j][3]);
        }
    }
    if (bx != by) {
        #pragma unroll
        for (int ia = 0; ia < 2; ia++) {
            int row = m0 + wm * 32 + ia * 16 + g;
            #pragma unroll
            for (int j = 0; j < 8; j++) {
                int col = n0 + wn * 64 + j * 8 + q * 2;
                Cb[(size_t)col * NN + row]           = acc[ia][j][0];
                Cb[(size_t)(col + 1) * NN + row]     = acc[ia][j][1];
                Cb[(size_t)col * NN + row + 8]       = acc[ia][j][2];
                Cb[(size_t)(col + 1) * NN + row + 8] = acc[ia][j][3];
            }
        }
    }
}

// ---------------- 5) radix-select top-64 (warp-aggregated atomics, pass 1) + fused output ----------------
__global__ void __launch_bounds__(256) topk_out_kernel(float* __restrict__ out)
{
    const int n = blockIdx.x;
    const int b = blockIdx.y;
    const int t = threadIdx.x;
    const int lane = t & 31;

    __shared__ int      hist[256];
    __shared__ unsigned sh_prefix;
    __shared__ int      sh_krem;
    __shared__ float    red_f[8];
    __shared__ int      sel_idx[KTOP];
    __shared__ unsigned sel_key[KTOP];
    __shared__ float    sel_w[KTOP];
    __shared__ int      eq_idx[128];
    __shared__ int      cnt_gt, cnt_eq;
    __shared__ float    Zsh;

    const float* row = g_cos + ((size_t)b * NN + n) * NN;

    unsigned kreg[16];
    #pragma unroll
    for (int j = 0; j < 4; j++) {
        float4 v = *(const float4*)&row[1024 * j + 4 * t];
        const float vv[4] = {v.x, v.y, v.z, v.w};
        #pragma unroll
        for (int q = 0; q < 4; q++) {
            unsigned x = __float_as_uint(vv[q]);
            kreg[4 * j + q] = (x & 0x80000000u) ? ~x : (x | 0x80000000u);
        }
    }
    if (t == 0) { sh_prefix = 0u; sh_krem = KTOP; cnt_gt = 0; cnt_eq = 0; }
    hist[t] = 0;
    __syncthreads();

    // ---- pass d=3: warp-aggregated atomics (match_any collapses same-bin lanes) ----
    #pragma unroll
    for (int j = 0; j < 16; j++) {
        unsigned bin = kreg[j] >> 24;
        unsigned mk = __match_any_sync(0xffffffffu, bin);
        int cnt = __popc(mk);
        if (lane == (__ffs(mk) - 1)) atomicAdd(&hist[bin], cnt);
    }
    __syncthreads();
    if (t < 32) {
        int bins[8], local = 0;
        #pragma unroll
        for (int i2 = 0; i2 < 8; i2++) { bins[i2] = hist[255 - 8 * t - i2]; local += bins[i2]; }
        int excl = local;
        #pragma unroll
        for (int o = 1; o < 32; o <<= 1) {
            int v = __shfl_up_sync(0xffffffffu, excl, o);
            if (t >= o) excl += v;
        }
        excl -= local;
        if (excl < KTOP && KTOP <= excl + local) {
            int run = excl, digit = 0, gt_before = excl;
            #pragma unroll
            for (int i2 = 0; i2 < 8; i2++) {
                if (run + bins[i2] >= KTOP) { digit = 255 - 8 * t - i2; gt_before = run; break; }
                run += bins[i2];
            }
            sh_prefix = (unsigned)digit << 24;
            sh_krem = KTOP - gt_before;
        }
    }
    __syncthreads();

    // ---- passes d=2..0: few participants, plain atomics ----
    #pragma unroll
    for (int d = 2; d >= 0; d--) {
        hist[t] = 0;
        __syncthreads();
        const unsigned prefix = sh_prefix;
        const int krem = sh_krem;
        const int shift = d * 8;
        const unsigned mask = 0xFFFFFFFFu << (8 * (d + 1));
        #pragma unroll
        for (int j = 0; j < 16; j++) {
            unsigned u = kreg[j];
            if ((u & mask) == prefix) atomicAdd(&hist[(u >> shift) & 0xFF], 1);
        }
        __syncthreads();
        if (t < 32) {
            int bins[8], local = 0;
            #pragma unroll
            for (int i2 = 0; i2 < 8; i2++) { bins[i2] = hist[255 - 8 * t - i2]; local += bins[i2]; }
            int excl = local;
            #pragma unroll
            for (int o = 1; o < 32; o <<= 1) {
                int v = __shfl_up_sync(0xffffffffu, excl, o);
                if (t >= o) excl += v;
            }
            excl -= local;
            if (excl < krem && krem <= excl + local) {
                int run = excl, digit = 0, gt_before = excl;
                #pragma unroll
                for (int i2 = 0; i2 < 8; i2++) {
                    if (run + bins[i2] >= krem) { digit = 255 - 8 * t - i2; gt_before = run; break; }
                    run += bins[i2];
                }
                sh_prefix = prefix | ((unsigned)digit << shift);
                sh_krem = krem - gt_before;
            }
        }
        __syncthreads();
    }
    const unsigned ustar = sh_prefix;
    const int r = sh_krem;

    #pragma unroll
    for (int j = 0; j < 16; j++) {
        unsigned u = kreg[j];
        int idx = ((j >> 2) << 10) + (t << 2) + (j & 3);
        if (u > ustar) {
            int p = atomicAdd(&cnt_gt, 1);
            sel_idx[p] = idx;
            sel_key[p] = u;
        } else if (u == ustar) {
            int p = atomicAdd(&cnt_eq, 1);
            if (p < 128) eq_idx[p] = idx;
        }
    }
    __syncthreads();

    const int ngt = cnt_gt;
    if (t == 0) {
        int ne = cnt_eq < 128 ? cnt_eq : 128;
        for (int a = 1; a < ne; a++) {
            int v = eq_idx[a]; int c2 = a - 1;
            while (c2 >= 0 && eq_idx[c2] > v) { eq_idx[c2 + 1] = eq_idx[c2]; c2--; }
            eq_idx[c2 + 1] = v;
        }
        for (int a = 0; a < r; a++) { sel_idx[ngt + a] = eq_idx[a]; sel_key[ngt + a] = ustar; }
    }
    __syncthreads();

    float e_val = 0.f;
    if (t < KTOP) {
        unsigned u = sel_key[t];
        float v = (u & 0x80000000u) ? __uint_as_float(u & 0x7FFFFFFFu) : __uint_as_float(~u);
        e_val = expf(v);
        sel_w[t] = e_val - 1.0f;
    }
    float s = e_val;
    #pragma unroll
    for (int o = 16; o; o >>= 1) s += __shfl_xor_sync(0xffffffffu, s, o);
    if ((t & 31) == 0) red_f[t >> 5] = s;
    __syncthreads();
    if (t == 0) {
        float z = (float)(NN - KTOP);
        #pragma unroll
        for (int w = 0; w < 8; w++) z += red_f[w];
        Zsh = z;
    }
    __syncthreads();

    const __nv_bfloat16* Vb = g_value + (size_t)b * NN * DD;
    float acc = g_sumv[b * DD + t];
    const float invZ = 1.0f / Zsh;
    #pragma unroll 8
    for (int k = 0; k < KTOP; k++)
        acc += sel_w[k] * __bfloat162float(Vb[(size_t)sel_idx[k] * DD + t]);
    out[((size_t)b * NN + n) * DD + t] = acc * invZ;
}

// ---------------- launch ----------------
extern "C" void kernel_launch(void* const* d_in, const int* in_sizes, int n_in,
                              void* d_out, int out_size)
{
    const float* x    = (const float*)d_in[0];
    const float* W    = (const float*)d_in[1];
    const float* bias = (const float*)d_in[2];
    float*       out  = (float*)d_out;

    float* p_cos;
    cudaGetSymbolAddress((void**)&p_cos, g_cos);

    const int MMA_SMEM = 3 * 32768;
    cudaFuncSetAttribute(cosmma_kernel,   cudaFuncAttributeMaxDynamicSharedMemorySize, MMA_SMEM);
    cudaFuncSetAttribute(valuemma_kernel, cudaFuncAttributeMaxDynamicSharedMemorySize, MMA_SMEM);

    normalize_pack_kernel<<<BB * NN, DD>>>(x, W);                                   // #1
    xsum_part_kernel<<<dim3(16, BB), DD>>>(x);                                      // #2
    valuemma_kernel<<<dim3(DD / 128, (BB * NN) / 128), 256, MMA_SMEM>>>(bias);      // #3
    cosmma_kernel<<<dim3((NN / 128) * (NN / 128 + 1) / 2, 1, BB), 256, MMA_SMEM>>>(p_cos);  // #4 (profiler)
    sumv_mv_kernel<<<BB, DD>>>(W, bias);                                            // #5
    topk_out_kernel<<<dim3(NN, BB), 256>>>(out);                                    // #6
}

// round 14
// speedup vs baseline: 1.3349x; 1.1294x over previous
#include <cuda_runtime.h>
#include <cuda_bf16.h>
#include <cstdint>
#include <math.h>

#define BB 4
#define NN 4096
#define DD 256
#define KTOP 64
#define EPSN 1e-12f

#define PACKW 512             // [hi(256) | lo(256)] per row
#define NCHUNK_V 12           // value: full 3-term split
#define NCHUNK_C 8            // cos: H·(H+L)^T

// ---------------- scratch ----------------
__device__ __nv_bfloat16  g_value[(size_t)BB * NN * DD];
__device__ float          g_cos  [(size_t)BB * NN * NN];
__device__ __nv_bfloat16  g_pack [(size_t)BB * NN * PACKW];
__device__ __nv_bfloat16  g_Wpack[(size_t)DD * PACKW];
__device__ float          g_norm [(size_t)BB * NN];
__device__ float          g_xsum_part[BB * 16 * DD];
__device__ float          g_sumv[BB * DD];

__device__ __constant__ int CAMAP_V[NCHUNK_V] = {0,1,2,3, 0,1,2,3, 4,5,6,7};
__device__ __constant__ int CBMAP_V[NCHUNK_V] = {0,1,2,3, 4,5,6,7, 0,1,2,3};

__device__ __forceinline__ uint32_t smem_to_u32(const void* p) {
    uint32_t a;
    asm("{ .reg .u64 t; cvta.to.shared.u64 t, %1; cvt.u32.u64 %0, t; }" : "=r"(a) : "l"(p));
    return a;
}
__device__ __forceinline__ void ldsm4(uint32_t& r0, uint32_t& r1, uint32_t& r2, uint32_t& r3, uint32_t addr) {
    asm volatile("ldmatrix.sync.aligned.m8n8.x4.shared.b16 {%0,%1,%2,%3}, [%4];"
        : "=r"(r0), "=r"(r1), "=r"(r2), "=r"(r3) : "r"(addr));
}
__device__ __forceinline__ void mma16816(float* d, const uint32_t* a, const uint32_t* b) {
    asm volatile("mma.sync.aligned.m16n8k16.row.col.f32.bf16.bf16.f32 "
        "{%0,%1,%2,%3}, {%4,%5,%6,%7}, {%8,%9}, {%0,%1,%2,%3};"
        : "+f"(d[0]), "+f"(d[1]), "+f"(d[2]), "+f"(d[3])
        : "r"(a[0]), "r"(a[1]), "r"(a[2]), "r"(a[3]), "r"(b[0]), "r"(b[1]));
}
__device__ __forceinline__ void cp_async16(uint32_t saddr, const void* gptr) {
    asm volatile("cp.async.cg.shared.global [%0], [%1], 16;" :: "r"(saddr), "l"(gptr) : "memory");
}
#define CP_COMMIT() asm volatile("cp.async.commit_group;" ::: "memory")
#define CP_WAIT(N)  asm volatile("cp.async.wait_group %0;" :: "n"(N) : "memory")

// ---------------- 1) normalize + hi/lo pack + norm save (+ W pack piggyback) ----------------
__global__ void __launch_bounds__(DD) normalize_pack_kernel(const float* __restrict__ x,
                                                            const float* __restrict__ W)
{
    int row = blockIdx.x;
    int d   = threadIdx.x;
    float v = x[(size_t)row * DD + d];
    float s = v * v;
    __shared__ float red[8];
    #pragma unroll
    for (int o = 16; o; o >>= 1) s += __shfl_xor_sync(0xffffffffu, s, o);
    if ((d & 31) == 0) red[d >> 5] = s;
    __syncthreads();
    if (d < 32) {
        float t = (d < 8) ? red[d] : 0.f;
        #pragma unroll
        for (int o = 4; o; o >>= 1) t += __shfl_xor_sync(0xffffffffu, t, o);
        if (d == 0) red[0] = t;
    }
    __syncthreads();
    float norm = sqrtf(red[0]);
    float nv = v / fmaxf(norm, EPSN);

    __nv_bfloat16 hi = __float2bfloat16(nv);
    __nv_bfloat16 lo = __float2bfloat16(nv - __bfloat162float(hi));

    size_t base = (size_t)row * PACKW;
    g_pack[base + d]       = hi;
    g_pack[base + 256 + d] = lo;
    if (d == 0) g_norm[row] = norm;

    if (row < DD) {
        float w = W[(size_t)row * DD + d];
        __nv_bfloat16 whi = __float2bfloat16(w);
        __nv_bfloat16 wlo = __float2bfloat16(w - __bfloat162float(whi));
        g_Wpack[(size_t)row * PACKW + d]       = whi;
        g_Wpack[(size_t)row * PACKW + 256 + d] = wlo;
    }
}

// ---------------- 1b) per-batch partial column sums of x ----------------
__global__ void __launch_bounds__(DD) xsum_part_kernel(const float* __restrict__ x)
{
    int b = blockIdx.y, c = blockIdx.x, e = threadIdx.x;
    const float* base = x + (size_t)b * NN * DD + (size_t)c * 256 * DD + e;
    float s = 0.f;
    #pragma unroll 8
    for (int n = 0; n < 256; n++) s += base[(size_t)n * DD];
    g_xsum_part[(b * 16 + c) * DD + e] = s;
}

// ---------------- 1c) sumv = (colsum x) @ W^T + N*b  (exact algebra) ----------------
__global__ void __launch_bounds__(DD) sumv_mv_kernel(const float* __restrict__ W,
                                                     const float* __restrict__ bias)
{
    int b = blockIdx.x, t = threadIdx.x;
    __shared__ float xs[DD];
    float s = 0.f;
    #pragma unroll
    for (int c = 0; c < 16; c++) s += g_xsum_part[(b * 16 + c) * DD + t];
    xs[t] = s;
    __syncthreads();
    float acc = 0.f;
    const float4* Wr = (const float4*)&W[(size_t)t * DD];
    #pragma unroll 8
    for (int d4 = 0; d4 < 64; d4++) {
        float4 w = Wr[d4];
        acc += xs[d4 * 4 + 0] * w.x + xs[d4 * 4 + 1] * w.y
             + xs[d4 * 4 + 2] * w.z + xs[d4 * 4 + 3] * w.w;
    }
    g_sumv[b * DD + t] = acc + (float)NN * bias[t];
}

// ---------------- 2) value = norm * (nx @ W^T) + b  -> bf16 ----------------
__global__ void __launch_bounds__(256, 2) valuemma_kernel(const float* __restrict__ bias)
{
    extern __shared__ char smem[];
    const uint32_t sb = smem_to_u32(smem);

    const int tid  = threadIdx.x;
    const int wid  = tid >> 5;
    const int lane = tid & 31;
    const int wm   = wid & 3;
    const int wn   = wid >> 2;
    const int m0   = blockIdx.y * 128;
    const int n0   = blockIdx.x * 128;

    const __nv_bfloat16* Agl = g_pack  + (size_t)m0 * PACKW;
    const __nv_bfloat16* Bgl = g_Wpack + (size_t)n0 * PACKW;

    const int lr = tid >> 3;
    const int lj = tid & 7;

    auto load_chunk_async = [&](int c, int s) {
        const char* ga = (const char*)Agl + (size_t)CAMAP_V[c] * 128;
        const char* gb = (const char*)Bgl + (size_t)CBMAP_V[c] * 128;
        uint32_t sa = sb + s * 32768;
        uint32_t sbm = sa + 16384;
        #pragma unroll
        for (int k = 0; k < 4; k++) {
            int r = lr + 32 * k;
            uint32_t off = r * 128 + ((lj ^ (r & 7)) << 4);
            cp_async16(sa + off,  ga + (size_t)r * (PACKW * 2) + lj * 16);
            cp_async16(sbm + off, gb + (size_t)r * (PACKW * 2) + lj * 16);
        }
    };

    float acc[2][8][4];
    #pragma unroll
    for (int ia = 0; ia < 2; ia++)
        #pragma unroll
        for (int j = 0; j < 8; j++)
            #pragma unroll
            for (int q = 0; q < 4; q++) acc[ia][j][q] = 0.f;

    const int arow_lo = (lane & 7) + ((lane >> 3) & 1) * 8;
    const int a_cc_add = (lane >> 4);
    const int brow_lo = (lane & 7) + ((lane >> 4) ? 8 : 0);
    const int b_cc_add = ((lane >> 3) & 1);

    load_chunk_async(0, 0); CP_COMMIT();
    load_chunk_async(1, 1); CP_COMMIT();

    for (int c = 0; c < NCHUNK_V; c++) {
        if (c + 1 < NCHUNK_V) { CP_WAIT(1); } else { CP_WAIT(0); }
        __syncthreads();
        if (c + 2 < NCHUNK_V) { load_chunk_async(c + 2, (c + 2) % 3); CP_COMMIT(); }

        const uint32_t abase = sb + (c % 3) * 32768;
        const uint32_t bbase = abase + 16384;

        #pragma unroll
        for (int ks = 0; ks < 4; ks++) {
            uint32_t af[2][4], bf[8][2];
            #pragma unroll
            for (int ia = 0; ia < 2; ia++) {
                int row = wm * 32 + ia * 16 + arow_lo;
                uint32_t cc = 2 * ks + a_cc_add;
                uint32_t addr = abase + row * 128 + ((cc << 4) ^ ((row & 7) << 4));
                ldsm4(af[ia][0], af[ia][1], af[ia][2], af[ia][3], addr);
            }
            #pragma unroll
            for (int L = 0; L < 4; L++) {
                int row = wn * 64 + L * 16 + brow_lo;
                uint32_t cc = 2 * ks + b_cc_add;
                uint32_t addr = bbase + row * 128 + ((cc << 4) ^ ((row & 7) << 4));
                ldsm4(bf[2 * L][0], bf[2 * L][1], bf[2 * L + 1][0], bf[2 * L + 1][1], addr);
            }
            #pragma unroll
            for (int ia = 0; ia < 2; ia++)
                #pragma unroll
                for (int j = 0; j < 8; j++)
                    mma16816(acc[ia][j], af[ia], bf[j]);
        }
    }

    const int g = lane >> 2, q = lane & 3;
    #pragma unroll
    for (int ia = 0; ia < 2; ia++) {
        int row = m0 + wm * 32 + ia * 16 + g;
        float nr0 = __ldg(&g_norm[row]);
        float nr8 = __ldg(&g_norm[row + 8]);
        #pragma unroll
        for (int j = 0; j < 8; j++) {
            int col = n0 + wn * 64 + j * 8 + q * 2;
            float b0 = __ldg(&bias[col]), b1 = __ldg(&bias[col + 1]);
            __nv_bfloat162 v01 = __floats2bfloat162_rn(acc[ia][j][0] * nr0 + b0, acc[ia][j][1] * nr0 + b1);
            __nv_bfloat162 v23 = __floats2bfloat162_rn(acc[ia][j][2] * nr8 + b0, acc[ia][j][3] * nr8 + b1);
            *(__nv_bfloat162*)&g_value[(size_t)row * DD + col]       = v01;
            *(__nv_bfloat162*)&g_value[(size_t)(row + 8) * DD + col] = v23;
        }
    }
}

// ---------------- 4) cos = H @ (H+L)^T  per batch (R8 config) ----------------
__global__ void __launch_bounds__(256, 2) cosmma_kernel(float* __restrict__ C, int b)
{
    extern __shared__ char smem[];
    const uint32_t sb = smem_to_u32(smem);

    const int tid  = threadIdx.x;
    const int wid  = tid >> 5;
    const int lane = tid & 31;
    const int wm   = wid & 3;
    const int wn   = wid >> 2;

    int i  = blockIdx.x;
    int by = (int)((sqrtf(8.f * (float)i + 1.f) - 1.f) * 0.5f);
    while ((by + 1) * (by + 2) / 2 <= i) by++;
    while (by * (by + 1) / 2 > i) by--;
    int bx = i - by * (by + 1) / 2;
    const int m0 = by * 128;
    const int n0 = bx * 128;

    const __nv_bfloat16* Agl = g_pack + ((size_t)b * NN + m0) * PACKW;
    const __nv_bfloat16* Bgl = g_pack + ((size_t)b * NN + n0) * PACKW;

    const int lr = tid >> 3;
    const int lj = tid & 7;

    auto load_chunk_async = [&](int c, int s) {
        const char* ga = (const char*)Agl + (size_t)(c & 3) * 128;   // hi only
        const char* gb = (const char*)Bgl + (size_t)c * 128;         // hi then lo
        uint32_t sa = sb + s * 32768;
        uint32_t sbm = sa + 16384;
        #pragma unroll
        for (int k = 0; k < 4; k++) {
            int r = lr + 32 * k;
            uint32_t off = r * 128 + ((lj ^ (r & 7)) << 4);
            cp_async16(sa + off,  ga + (size_t)r * (PACKW * 2) + lj * 16);
            cp_async16(sbm + off, gb + (size_t)r * (PACKW * 2) + lj * 16);
        }
    };

    float acc[2][8][4];
    #pragma unroll
    for (int ia = 0; ia < 2; ia++)
        #pragma unroll
        for (int j = 0; j < 8; j++)
            #pragma unroll
            for (int q = 0; q < 4; q++) acc[ia][j][q] = 0.f;

    const int arow_lo = (lane & 7) + ((lane >> 3) & 1) * 8;
    const int a_cc_add = (lane >> 4);
    const int brow_lo = (lane & 7) + ((lane >> 4) ? 8 : 0);
    const int b_cc_add = ((lane >> 3) & 1);

    load_chunk_async(0, 0); CP_COMMIT();
    load_chunk_async(1, 1); CP_COMMIT();

    for (int c = 0; c < NCHUNK_C; c++) {
        if (c + 1 < NCHUNK_C) { CP_WAIT(1); } else { CP_WAIT(0); }
        __syncthreads();
        if (c + 2 < NCHUNK_C) { load_chunk_async(c + 2, (c + 2) % 3); CP_COMMIT(); }

        const uint32_t abase = sb + (c % 3) * 32768;
        const uint32_t bbase = abase + 16384;

        #pragma unroll
        for (int ks = 0; ks < 4; ks++) {
            uint32_t af[2][4], bf[8][2];
            #pragma unroll
            for (int ia = 0; ia < 2; ia++) {
                int row = wm * 32 + ia * 16 + arow_lo;
                uint32_t cc = 2 * ks + a_cc_add;
                uint32_t addr = abase + row * 128 + ((cc << 4) ^ ((row & 7) << 4));
                ldsm4(af[ia][0], af[ia][1], af[ia][2], af[ia][3], addr);
            }
            #pragma unroll
            for (int L = 0; L < 4; L++) {
                int row = wn * 64 + L * 16 + brow_lo;
                uint32_t cc = 2 * ks + b_cc_add;
                uint32_t addr = bbase + row * 128 + ((cc << 4) ^ ((row & 7) << 4));
                ldsm4(bf[2 * L][0], bf[2 * L][1], bf[2 * L + 1][0], bf[2 * L + 1][1], addr);
            }
            #pragma unroll
            for (int ia = 0; ia < 2; ia++)
                #pragma unroll
                for (int j = 0; j < 8; j++)
                    mma16816(acc[ia][j], af[ia], bf[j]);
        }
    }

    float* Cb = C + (size_t)b * NN * NN;
    const int g = lane >> 2, q = lane & 3;
    #pragma unroll
    for (int ia = 0; ia < 2; ia++) {
        int row = m0 + wm * 32 + ia * 16 + g;
        #pragma unroll
        for (int j = 0; j < 8; j++) {
            int col = n0 + wn * 64 + j * 8 + q * 2;
            *(float2*)&Cb[(size_t)row * NN + col]       = make_float2(acc[ia][j][0], acc[ia][j][1]);
            *(float2*)&Cb[(size_t)(row + 8) * NN + col] = make_float2(acc[ia][j][2], acc[ia][j][3]);
        }
    }
    if (bx != by) {
        #pragma unroll
        for (int ia = 0; ia < 2; ia++) {
            int row = m0 + wm * 32 + ia * 16 + g;
            #pragma unroll
            for (int j = 0; j < 8; j++) {
                int col = n0 + wn * 64 + j * 8 + q * 2;
                Cb[(size_t)col * NN + row]           = acc[ia][j][0];
                Cb[(size_t)(col + 1) * NN + row]     = acc[ia][j][1];
                Cb[(size_t)col * NN + row + 8]       = acc[ia][j][2];
                Cb[(size_t)(col + 1) * NN + row + 8] = acc[ia][j][3];
            }
        }
    }
}

// ---------------- 5) radix-select top-64 (R10 plain version) + fused output; per batch ----------------
__global__ void __launch_bounds__(256) topk_out_kernel(float* __restrict__ out, int b)
{
    const int n = blockIdx.x;
    const int t = threadIdx.x;

    __shared__ int      hist[256];
    __shared__ unsigned sh_prefix;
    __shared__ int      sh_krem;
    __shared__ float    red_f[8];
    __shared__ int      sel_idx[KTOP];
    __shared__ unsigned sel_key[KTOP];
    __shared__ float    sel_w[KTOP];
    __shared__ int      eq_idx[128];
    __shared__ int      cnt_gt, cnt_eq;
    __shared__ float    Zsh;

    const float* row = g_cos + ((size_t)b * NN + n) * NN;

    unsigned kreg[16];
    #pragma unroll
    for (int j = 0; j < 4; j++) {
        float4 v = *(const float4*)&row[1024 * j + 4 * t];
        const float vv[4] = {v.x, v.y, v.z, v.w};
        #pragma unroll
        for (int q = 0; q < 4; q++) {
            unsigned x = __float_as_uint(vv[q]);
            kreg[4 * j + q] = (x & 0x80000000u) ? ~x : (x | 0x80000000u);
        }
    }
    if (t == 0) { sh_prefix = 0u; sh_krem = KTOP; cnt_gt = 0; cnt_eq = 0; }
    __syncthreads();

    #pragma unroll
    for (int d = 3; d >= 0; d--) {
        hist[t] = 0;
        __syncthreads();
        const unsigned prefix = sh_prefix;
        const int krem = sh_krem;
        const int shift = d * 8;
        const unsigned mask = (d == 3) ? 0u : (0xFFFFFFFFu << (8 * (d + 1)));
        #pragma unroll
        for (int j = 0; j < 16; j++) {
            unsigned u = kreg[j];
            if ((u & mask) == prefix) atomicAdd(&hist[(u >> shift) & 0xFF], 1);
        }
        __syncthreads();
        if (t < 32) {
            int bins[8], local = 0;
            #pragma unroll
            for (int i2 = 0; i2 < 8; i2++) { bins[i2] = hist[255 - 8 * t - i2]; local += bins[i2]; }
            int excl = local;
            #pragma unroll
            for (int o = 1; o < 32; o <<= 1) {
                int v = __shfl_up_sync(0xffffffffu, excl, o);
                if (t >= o) excl += v;
            }
            excl -= local;
            if (excl < krem && krem <= excl + local) {
                int run = excl, digit = 0, gt_before = excl;
                #pragma unroll
                for (int i2 = 0; i2 < 8; i2++) {
                    if (run + bins[i2] >= krem) { digit = 255 - 8 * t - i2; gt_before = run; break; }
                    run += bins[i2];
                }
                sh_prefix = prefix | ((unsigned)digit << shift);
                sh_krem = krem - gt_before;
            }
        }
        __syncthreads();
    }
    const unsigned ustar = sh_prefix;
    const int r = sh_krem;

    #pragma unroll
    for (int j = 0; j < 16; j++) {
        unsigned u = kreg[j];
        int idx = ((j >> 2) << 10) + (t << 2) + (j & 3);
        if (u > ustar) {
            int p = atomicAdd(&cnt_gt, 1);
            sel_idx[p] = idx;
            sel_key[p] = u;
        } else if (u == ustar) {
            int p = atomicAdd(&cnt_eq, 1);
            if (p < 128) eq_idx[p] = idx;
        }
    }
    __syncthreads();

    const int ngt = cnt_gt;
    if (t == 0) {
        int ne = cnt_eq < 128 ? cnt_eq : 128;
        for (int a = 1; a < ne; a++) {
            int v = eq_idx[a]; int c2 = a - 1;
            while (c2 >= 0 && eq_idx[c2] > v) { eq_idx[c2 + 1] = eq_idx[c2]; c2--; }
            eq_idx[c2 + 1] = v;
        }
        for (int a = 0; a < r; a++) { sel_idx[ngt + a] = eq_idx[a]; sel_key[ngt + a] = ustar; }
    }
    __syncthreads();

    float e_val = 0.f;
    if (t < KTOP) {
        unsigned u = sel_key[t];
        float v = (u & 0x80000000u) ? __uint_as_float(u & 0x7FFFFFFFu) : __uint_as_float(~u);
        e_val = expf(v);
        sel_w[t] = e_val - 1.0f;
    }
    float s = e_val;
    #pragma unroll
    for (int o = 16; o; o >>= 1) s += __shfl_xor_sync(0xffffffffu, s, o);
    if ((t & 31) == 0) red_f[t >> 5] = s;
    __syncthreads();
    if (t == 0) {
        float z = (float)(NN - KTOP);
        #pragma unroll
        for (int w = 0; w < 8; w++) z += red_f[w];
        Zsh = z;
    }
    __syncthreads();

    const __nv_bfloat16* Vb = g_value + (size_t)b * NN * DD;
    float acc = g_sumv[b * DD + t];
    const float invZ = 1.0f / Zsh;
    #pragma unroll 8
    for (int k = 0; k < KTOP; k++)
        acc += sel_w[k] * __bfloat162float(Vb[(size_t)sel_idx[k] * DD + t]);
    out[((size_t)b * NN + n) * DD + t] = acc * invZ;
}

// ---------------- launch: two-stream per-batch pipeline ----------------
extern "C" void kernel_launch(void* const* d_in, const int* in_sizes, int n_in,
                              void* d_out, int out_size)
{
    const float* x    = (const float*)d_in[0];
    const float* W    = (const float*)d_in[1];
    const float* bias = (const float*)d_in[2];
    float*       out  = (float*)d_out;

    float* p_cos;
    cudaGetSymbolAddress((void**)&p_cos, g_cos);

    // one-time resources (created on the uncaptured correctness call)
    static bool init_done = false;
    static cudaStream_t s1;
    static cudaEvent_t ev_pack, ev_cos[BB], ev_join;
    if (!init_done) {
        cudaStreamCreateWithFlags(&s1, cudaStreamNonBlocking);
        cudaEventCreateWithFlags(&ev_pack, cudaEventDisableTiming);
        for (int b = 0; b < BB; b++) cudaEventCreateWithFlags(&ev_cos[b], cudaEventDisableTiming);
        cudaEventCreateWithFlags(&ev_join, cudaEventDisableTiming);

        const int MMA_SMEM = 3 * 32768;
        cudaFuncSetAttribute(cosmma_kernel,   cudaFuncAttributeMaxDynamicSharedMemorySize, MMA_SMEM);
        cudaFuncSetAttribute(valuemma_kernel, cudaFuncAttributeMaxDynamicSharedMemorySize, MMA_SMEM);
        init_done = true;
    }
    const int MMA_SMEM = 3 * 32768;
    const int COS_GRID = (NN / 128) * (NN / 128 + 1) / 2;   // 528

    // s0 (capture/default stream): pack, then cos per batch
    normalize_pack_kernel<<<BB * NN, DD>>>(x, W);
    cudaEventRecord(ev_pack, 0);
    for (int b = 0; b < BB; b++) {
        cosmma_kernel<<<COS_GRID, 256, MMA_SMEM>>>(p_cos, b);
        cudaEventRecord(ev_cos[b], 0);
    }

    // s1: prologue for topk (xsum needs only x; valuemma needs pack), then topk per batch
    xsum_part_kernel<<<dim3(16, BB), DD, 0, s1>>>(x);
    cudaStreamWaitEvent(s1, ev_pack, 0);
    valuemma_kernel<<<dim3(DD / 128, (BB * NN) / 128), 256, MMA_SMEM, s1>>>(bias);
    sumv_mv_kernel<<<BB, DD, 0, s1>>>(W, bias);
    for (int b = 0; b < BB; b++) {
        cudaStreamWaitEvent(s1, ev_cos[b], 0);
        topk_out_kernel<<<NN, 256, 0, s1>>>(out, b);
    }

    // join s1 back into the capture stream
    cudaEventRecord(ev_join, s1);
    cudaStreamWaitEvent(0, ev_join, 0);
}

// round 15
// speedup vs baseline: 1.5371x; 1.1515x over previous
#include <cuda_runtime.h>
#include <cuda_fp16.h>
#include <cuda_bf16.h>
#include <cstdint>
#include <math.h>

#define BB 4
#define NN 4096
#define DD 256
#define KTOP 64
#define EPSN 1e-12f

#define PACKW 256             // fp16 row (no hi/lo split needed at 11-bit mantissa)
#define NCHUNK 4              // K=256 in 64-element chunks

// ---------------- scratch ----------------
__device__ __nv_bfloat16  g_value[(size_t)BB * NN * DD];
__device__ float          g_cos  [(size_t)BB * NN * NN];
__device__ __half         g_pack [(size_t)BB * NN * PACKW];     // 8.4 MB
__device__ __half         g_Wpack[(size_t)DD * PACKW];
__device__ float          g_norm [(size_t)BB * NN];
__device__ float          g_xsum_part[BB * 16 * DD];
__device__ float          g_sumv[BB * DD];

__device__ __forceinline__ uint32_t smem_to_u32(const void* p) {
    uint32_t a;
    asm("{ .reg .u64 t; cvta.to.shared.u64 t, %1; cvt.u32.u64 %0, t; }" : "=r"(a) : "l"(p));
    return a;
}
__device__ __forceinline__ void ldsm4(uint32_t& r0, uint32_t& r1, uint32_t& r2, uint32_t& r3, uint32_t addr) {
    asm volatile("ldmatrix.sync.aligned.m8n8.x4.shared.b16 {%0,%1,%2,%3}, [%4];"
        : "=r"(r0), "=r"(r1), "=r"(r2), "=r"(r3) : "r"(addr));
}
__device__ __forceinline__ void mma16816(float* d, const uint32_t* a, const uint32_t* b) {
    asm volatile("mma.sync.aligned.m16n8k16.row.col.f32.f16.f16.f32 "
        "{%0,%1,%2,%3}, {%4,%5,%6,%7}, {%8,%9}, {%0,%1,%2,%3};"
        : "+f"(d[0]), "+f"(d[1]), "+f"(d[2]), "+f"(d[3])
        : "r"(a[0]), "r"(a[1]), "r"(a[2]), "r"(a[3]), "r"(b[0]), "r"(b[1]));
}
__device__ __forceinline__ void cp_async16(uint32_t saddr, const void* gptr) {
    asm volatile("cp.async.cg.shared.global [%0], [%1], 16;" :: "r"(saddr), "l"(gptr) : "memory");
}
#define CP_COMMIT() asm volatile("cp.async.commit_group;" ::: "memory")
#define CP_WAIT(N)  asm volatile("cp.async.wait_group %0;" :: "n"(N) : "memory")

// ---------------- 1) normalize + fp16 pack + norm save (+ W pack piggyback) ----------------
__global__ void __launch_bounds__(DD) normalize_pack_kernel(const float* __restrict__ x,
                                                            const float* __restrict__ W)
{
    int row = blockIdx.x;
    int d   = threadIdx.x;
    float v = x[(size_t)row * DD + d];
    float s = v * v;
    __shared__ float red[8];
    #pragma unroll
    for (int o = 16; o; o >>= 1) s += __shfl_xor_sync(0xffffffffu, s, o);
    if ((d & 31) == 0) red[d >> 5] = s;
    __syncthreads();
    if (d < 32) {
        float t = (d < 8) ? red[d] : 0.f;
        #pragma unroll
        for (int o = 4; o; o >>= 1) t += __shfl_xor_sync(0xffffffffu, t, o);
        if (d == 0) red[0] = t;
    }
    __syncthreads();
    float norm = sqrtf(red[0]);
    float nv = v / fmaxf(norm, EPSN);

    g_pack[(size_t)row * PACKW + d] = __float2half(nv);
    if (d == 0) g_norm[row] = norm;

    if (row < DD)
        g_Wpack[(size_t)row * PACKW + d] = __float2half(W[(size_t)row * DD + d]);
}

// ---------------- 1b) per-batch partial column sums of x ----------------
__global__ void __launch_bounds__(DD) xsum_part_kernel(const float* __restrict__ x)
{
    int b = blockIdx.y, c = blockIdx.x, e = threadIdx.x;
    const float* base = x + (size_t)b * NN * DD + (size_t)c * 256 * DD + e;
    float s = 0.f;
    #pragma unroll 8
    for (int n = 0; n < 256; n++) s += base[(size_t)n * DD];
    g_xsum_part[(b * 16 + c) * DD + e] = s;
}

// ---------------- 1c) sumv = (colsum x) @ W^T + N*b  (exact algebra) ----------------
__global__ void __launch_bounds__(DD) sumv_mv_kernel(const float* __restrict__ W,
                                                     const float* __restrict__ bias)
{
    int b = blockIdx.x, t = threadIdx.x;
    __shared__ float xs[DD];
    float s = 0.f;
    #pragma unroll
    for (int c = 0; c < 16; c++) s += g_xsum_part[(b * 16 + c) * DD + t];
    xs[t] = s;
    __syncthreads();
    float acc = 0.f;
    const float4* Wr = (const float4*)&W[(size_t)t * DD];
    #pragma unroll 8
    for (int d4 = 0; d4 < 64; d4++) {
        float4 w = Wr[d4];
        acc += xs[d4 * 4 + 0] * w.x + xs[d4 * 4 + 1] * w.y
             + xs[d4 * 4 + 2] * w.z + xs[d4 * 4 + 3] * w.w;
    }
    g_sumv[b * DD + t] = acc + (float)NN * bias[t];
}

// ---------------- 2) value = norm * (nx @ W^T) + b  -> bf16  (fp16 mma, K=256) ----------------
__global__ void __launch_bounds__(256, 2) valuemma_kernel(const float* __restrict__ bias)
{
    extern __shared__ char smem[];
    const uint32_t sb = smem_to_u32(smem);

    const int tid  = threadIdx.x;
    const int wid  = tid >> 5;
    const int lane = tid & 31;
    const int wm   = wid & 3;
    const int wn   = wid >> 2;
    const int m0   = blockIdx.y * 128;
    const int n0   = blockIdx.x * 128;

    const __half* Agl = g_pack  + (size_t)m0 * PACKW;
    const __half* Bgl = g_Wpack + (size_t)n0 * PACKW;

    const int lr = tid >> 3;
    const int lj = tid & 7;

    auto load_chunk_async = [&](int c, int s) {
        const char* ga = (const char*)Agl + (size_t)c * 128;
        const char* gb = (const char*)Bgl + (size_t)c * 128;
        uint32_t sa = sb + s * 32768;
        uint32_t sbm = sa + 16384;
        #pragma unroll
        for (int k = 0; k < 4; k++) {
            int r = lr + 32 * k;
            uint32_t off = r * 128 + ((lj ^ (r & 7)) << 4);
            cp_async16(sa + off,  ga + (size_t)r * (PACKW * 2) + lj * 16);
            cp_async16(sbm + off, gb + (size_t)r * (PACKW * 2) + lj * 16);
        }
    };

    float acc[2][8][4];
    #pragma unroll
    for (int ia = 0; ia < 2; ia++)
        #pragma unroll
        for (int j = 0; j < 8; j++)
            #pragma unroll
            for (int q = 0; q < 4; q++) acc[ia][j][q] = 0.f;

    const int arow_lo = (lane & 7) + ((lane >> 3) & 1) * 8;
    const int a_cc_add = (lane >> 4);
    const int brow_lo = (lane & 7) + ((lane >> 4) ? 8 : 0);
    const int b_cc_add = ((lane >> 3) & 1);

    load_chunk_async(0, 0); CP_COMMIT();
    load_chunk_async(1, 1); CP_COMMIT();

    for (int c = 0; c < NCHUNK; c++) {
        if (c + 1 < NCHUNK) { CP_WAIT(1); } else { CP_WAIT(0); }
        __syncthreads();
        if (c + 2 < NCHUNK) { load_chunk_async(c + 2, (c + 2) % 3); CP_COMMIT(); }

        const uint32_t abase = sb + (c % 3) * 32768;
        const uint32_t bbase = abase + 16384;

        #pragma unroll
        for (int ks = 0; ks < 4; ks++) {
            uint32_t af[2][4], bf[8][2];
            #pragma unroll
            for (int ia = 0; ia < 2; ia++) {
                int row = wm * 32 + ia * 16 + arow_lo;
                uint32_t cc = 2 * ks + a_cc_add;
                uint32_t addr = abase + row * 128 + ((cc << 4) ^ ((row & 7) << 4));
                ldsm4(af[ia][0], af[ia][1], af[ia][2], af[ia][3], addr);
            }
            #pragma unroll
            for (int L = 0; L < 4; L++) {
                int row = wn * 64 + L * 16 + brow_lo;
                uint32_t cc = 2 * ks + b_cc_add;
                uint32_t addr = bbase + row * 128 + ((cc << 4) ^ ((row & 7) << 4));
                ldsm4(bf[2 * L][0], bf[2 * L][1], bf[2 * L + 1][0], bf[2 * L + 1][1], addr);
            }
            #pragma unroll
            for (int ia = 0; ia < 2; ia++)
                #pragma unroll
                for (int j = 0; j < 8; j++)
                    mma16816(acc[ia][j], af[ia], bf[j]);
        }
    }

    const int g = lane >> 2, q = lane & 3;
    #pragma unroll
    for (int ia = 0; ia < 2; ia++) {
        int row = m0 + wm * 32 + ia * 16 + g;
        float nr0 = __ldg(&g_norm[row]);
        float nr8 = __ldg(&g_norm[row + 8]);
        #pragma unroll
        for (int j = 0; j < 8; j++) {
            int col = n0 + wn * 64 + j * 8 + q * 2;
            float b0 = __ldg(&bias[col]), b1 = __ldg(&bias[col + 1]);
            __nv_bfloat162 v01 = __floats2bfloat162_rn(acc[ia][j][0] * nr0 + b0, acc[ia][j][1] * nr0 + b1);
            __nv_bfloat162 v23 = __floats2bfloat162_rn(acc[ia][j][2] * nr8 + b0, acc[ia][j][3] * nr8 + b1);
            *(__nv_bfloat162*)&g_value[(size_t)row * DD + col]       = v01;
            *(__nv_bfloat162*)&g_value[(size_t)(row + 8) * DD + col] = v23;
        }
    }
}

// ---------------- 4) cos = nx @ nx^T  (fp16 mma, K=256, per batch, triangle+mirror) ----------------
__global__ void __launch_bounds__(256, 2) cosmma_kernel(float* __restrict__ C, int b)
{
    extern __shared__ char smem[];
    const uint32_t sb = smem_to_u32(smem);

    const int tid  = threadIdx.x;
    const int wid  = tid >> 5;
    const int lane = tid & 31;
    const int wm   = wid & 3;
    const int wn   = wid >> 2;

    int i  = blockIdx.x;
    int by = (int)((sqrtf(8.f * (float)i + 1.f) - 1.f) * 0.5f);
    while ((by + 1) * (by + 2) / 2 <= i) by++;
    while (by * (by + 1) / 2 > i) by--;
    int bx = i - by * (by + 1) / 2;
    const int m0 = by * 128;
    const int n0 = bx * 128;

    const __half* Agl = g_pack + ((size_t)b * NN + m0) * PACKW;
    const __half* Bgl = g_pack + ((size_t)b * NN + n0) * PACKW;

    const int lr = tid >> 3;
    const int lj = tid & 7;

    auto load_chunk_async = [&](int c, int s) {
        const char* ga = (const char*)Agl + (size_t)c * 128;
        const char* gb = (const char*)Bgl + (size_t)c * 128;
        uint32_t sa = sb + s * 32768;
        uint32_t sbm = sa + 16384;
        #pragma unroll
        for (int k = 0; k < 4; k++) {
            int r = lr + 32 * k;
            uint32_t off = r * 128 + ((lj ^ (r & 7)) << 4);
            cp_async16(sa + off,  ga + (size_t)r * (PACKW * 2) + lj * 16);
            cp_async16(sbm + off, gb + (size_t)r * (PACKW * 2) + lj * 16);
        }
    };

    float acc[2][8][4];
    #pragma unroll
    for (int ia = 0; ia < 2; ia++)
        #pragma unroll
        for (int j = 0; j < 8; j++)
            #pragma unroll
            for (int q = 0; q < 4; q++) acc[ia][j][q] = 0.f;

    const int arow_lo = (lane & 7) + ((lane >> 3) & 1) * 8;
    const int a_cc_add = (lane >> 4);
    const int brow_lo = (lane & 7) + ((lane >> 4) ? 8 : 0);
    const int b_cc_add = ((lane >> 3) & 1);

    load_chunk_async(0, 0); CP_COMMIT();
    load_chunk_async(1, 1); CP_COMMIT();

    for (int c = 0; c < NCHUNK; c++) {
        if (c + 1 < NCHUNK) { CP_WAIT(1); } else { CP_WAIT(0); }
        __syncthreads();
        if (c + 2 < NCHUNK) { load_chunk_async(c + 2, (c + 2) % 3); CP_COMMIT(); }

        const uint32_t abase = sb + (c % 3) * 32768;
        const uint32_t bbase = abase + 16384;

        #pragma unroll
        for (int ks = 0; ks < 4; ks++) {
            uint32_t af[2][4], bf[8][2];
            #pragma unroll
            for (int ia = 0; ia < 2; ia++) {
                int row = wm * 32 + ia * 16 + arow_lo;
                uint32_t cc = 2 * ks + a_cc_add;
                uint32_t addr = abase + row * 128 + ((cc << 4) ^ ((row & 7) << 4));
                ldsm4(af[ia][0], af[ia][1], af[ia][2], af[ia][3], addr);
            }
            #pragma unroll
            for (int L = 0; L < 4; L++) {
                int row = wn * 64 + L * 16 + brow_lo;
                uint32_t cc = 2 * ks + b_cc_add;
                uint32_t addr = bbase + row * 128 + ((cc << 4) ^ ((row & 7) << 4));
                ldsm4(bf[2 * L][0], bf[2 * L][1], bf[2 * L + 1][0], bf[2 * L + 1][1], addr);
            }
            #pragma unroll
            for (int ia = 0; ia < 2; ia++)
                #pragma unroll
                for (int j = 0; j < 8; j++)
                    mma16816(acc[ia][j], af[ia], bf[j]);
        }
    }

    float* Cb = C + (size_t)b * NN * NN;
    const int g = lane >> 2, q = lane & 3;
    #pragma unroll
    for (int ia = 0; ia < 2; ia++) {
        int row = m0 + wm * 32 + ia * 16 + g;
        #pragma unroll
        for (int j = 0; j < 8; j++) {
            int col = n0 + wn * 64 + j * 8 + q * 2;
            *(float2*)&Cb[(size_t)row * NN + col]       = make_float2(acc[ia][j][0], acc[ia][j][1]);
            *(float2*)&Cb[(size_t)(row + 8) * NN + col] = make_float2(acc[ia][j][2], acc[ia][j][3]);
        }
    }
    if (bx != by) {
        #pragma unroll
        for (int ia = 0; ia < 2; ia++) {
            int row = m0 + wm * 32 + ia * 16 + g;
            #pragma unroll
            for (int j = 0; j < 8; j++) {
                int col = n0 + wn * 64 + j * 8 + q * 2;
                Cb[(size_t)col * NN + row]           = acc[ia][j][0];
                Cb[(size_t)(col + 1) * NN + row]     = acc[ia][j][1];
                Cb[(size_t)col * NN + row + 8]       = acc[ia][j][2];
                Cb[(size_t)(col + 1) * NN + row + 8] = acc[ia][j][3];
            }
        }
    }
}

// ---------------- 5) radix-select top-64 + fused output; per batch ----------------
__global__ void __launch_bounds__(256) topk_out_kernel(float* __restrict__ out, int b)
{
    const int n = blockIdx.x;
    const int t = threadIdx.x;

    __shared__ int      hist[256];
    __shared__ unsigned sh_prefix;
    __shared__ int      sh_krem;
    __shared__ float    red_f[8];
    __shared__ int      sel_idx[KTOP];
    __shared__ unsigned sel_key[KTOP];
    __shared__ float    sel_w[KTOP];
    __shared__ int      eq_idx[128];
    __shared__ int      cnt_gt, cnt_eq;
    __shared__ float    Zsh;

    const float* row = g_cos + ((size_t)b * NN + n) * NN;

    unsigned kreg[16];
    #pragma unroll
    for (int j = 0; j < 4; j++) {
        float4 v = *(const float4*)&row[1024 * j + 4 * t];
        const float vv[4] = {v.x, v.y, v.z, v.w};
        #pragma unroll
        for (int q = 0; q < 4; q++) {
            unsigned x = __float_as_uint(vv[q]);
            kreg[4 * j + q] = (x & 0x80000000u) ? ~x : (x | 0x80000000u);
        }
    }
    if (t == 0) { sh_prefix = 0u; sh_krem = KTOP; cnt_gt = 0; cnt_eq = 0; }
    __syncthreads();

    #pragma unroll
    for (int d = 3; d >= 0; d--) {
        hist[t] = 0;
        __syncthreads();
        const unsigned prefix = sh_prefix;
        const int krem = sh_krem;
        const int shift = d * 8;
        const unsigned mask = (d == 3) ? 0u : (0xFFFFFFFFu << (8 * (d + 1)));
        #pragma unroll
        for (int j = 0; j < 16; j++) {
            unsigned u = kreg[j];
            if ((u & mask) == prefix) atomicAdd(&hist[(u >> shift) & 0xFF], 1);
        }
        __syncthreads();
        if (t < 32) {
            int bins[8], local = 0;
            #pragma unroll
            for (int i2 = 0; i2 < 8; i2++) { bins[i2] = hist[255 - 8 * t - i2]; local += bins[i2]; }
            int excl = local;
            #pragma unroll
            for (int o = 1; o < 32; o <<= 1) {
                int v = __shfl_up_sync(0xffffffffu, excl, o);
                if (t >= o) excl += v;
            }
            excl -= local;
            if (excl < krem && krem <= excl + local) {
                int run = excl, digit = 0, gt_before = excl;
                #pragma unroll
                for (int i2 = 0; i2 < 8; i2++) {
                    if (run + bins[i2] >= krem) { digit = 255 - 8 * t - i2; gt_before = run; break; }
                    run += bins[i2];
                }
                sh_prefix = prefix | ((unsigned)digit << shift);
                sh_krem = krem - gt_before;
            }
        }
        __syncthreads();
    }
    const unsigned ustar = sh_prefix;
    const int r = sh_krem;

    #pragma unroll
    for (int j = 0; j < 16; j++) {
        unsigned u = kreg[j];
        int idx = ((j >> 2) << 10) + (t << 2) + (j & 3);
        if (u > ustar) {
            int p = atomicAdd(&cnt_gt, 1);
            sel_idx[p] = idx;
            sel_key[p] = u;
        } else if (u == ustar) {
            int p = atomicAdd(&cnt_eq, 1);
            if (p < 128) eq_idx[p] = idx;
        }
    }
    __syncthreads();

    const int ngt = cnt_gt;
    if (t == 0) {
        int ne = cnt_eq < 128 ? cnt_eq : 128;
        for (int a = 1; a < ne; a++) {
            int v = eq_idx[a]; int c2 = a - 1;
            while (c2 >= 0 && eq_idx[c2] > v) { eq_idx[c2 + 1] = eq_idx[c2]; c2--; }
            eq_idx[c2 + 1] = v;
        }
        for (int a = 0; a < r; a++) { sel_idx[ngt + a] = eq_idx[a]; sel_key[ngt + a] = ustar; }
    }
    __syncthreads();

    float e_val = 0.f;
    if (t < KTOP) {
        unsigned u = sel_key[t];
        float v = (u & 0x80000000u) ? __uint_as_float(u & 0x7FFFFFFFu) : __uint_as_float(~u);
        e_val = expf(v);
        sel_w[t] = e_val - 1.0f;
    }
    float s = e_val;
    #pragma unroll
    for (int o = 16; o; o >>= 1) s += __shfl_xor_sync(0xffffffffu, s, o);
    if ((t & 31) == 0) red_f[t >> 5] = s;
    __syncthreads();
    if (t == 0) {
        float z = (float)(NN - KTOP);
        #pragma unroll
        for (int w = 0; w < 8; w++) z += red_f[w];
        Zsh = z;
    }
    __syncthreads();

    const __nv_bfloat16* Vb = g_value + (size_t)b * NN * DD;
    float acc = g_sumv[b * DD + t];
    const float invZ = 1.0f / Zsh;
    #pragma unroll 8
    for (int k = 0; k < KTOP; k++)
        acc += sel_w[k] * __bfloat162float(Vb[(size_t)sel_idx[k] * DD + t]);
    out[((size_t)b * NN + n) * DD + t] = acc * invZ;
}

// ---------------- launch: two-stream per-batch pipeline ----------------
extern "C" void kernel_launch(void* const* d_in, const int* in_sizes, int n_in,
                              void* d_out, int out_size)
{
    const float* x    = (const float*)d_in[0];
    const float* W    = (const float*)d_in[1];
    const float* bias = (const float*)d_in[2];
    float*       out  = (float*)d_out;

    float* p_cos;
    cudaGetSymbolAddress((void**)&p_cos, g_cos);

    static bool init_done = false;
    static cudaStream_t s1;
    static cudaEvent_t ev_pack, ev_cos[BB], ev_join;
    if (!init_done) {
        cudaStreamCreateWithFlags(&s1, cudaStreamNonBlocking);
        cudaEventCreateWithFlags(&ev_pack, cudaEventDisableTiming);
        for (int b = 0; b < BB; b++) cudaEventCreateWithFlags(&ev_cos[b], cudaEventDisableTiming);
        cudaEventCreateWithFlags(&ev_join, cudaEventDisableTiming);

        const int SM = 3 * 32768;
        cudaFuncSetAttribute(cosmma_kernel,   cudaFuncAttributeMaxDynamicSharedMemorySize, SM);
        cudaFuncSetAttribute(valuemma_kernel, cudaFuncAttributeMaxDynamicSharedMemorySize, SM);
        init_done = true;
    }
    const int MMA_SMEM = 3 * 32768;
    const int COS_GRID = (NN / 128) * (NN / 128 + 1) / 2;   // 528

    // s0: pack, then cos per batch
    normalize_pack_kernel<<<BB * NN, DD>>>(x, W);
    cudaEventRecord(ev_pack, 0);
    for (int b = 0; b < BB; b++) {
        cosmma_kernel<<<COS_GRID, 256, MMA_SMEM>>>(p_cos, b);
        cudaEventRecord(ev_cos[b], 0);
    }

    // s1: topk prologue, then topk per batch gated on cos events
    xsum_part_kernel<<<dim3(16, BB), DD, 0, s1>>>(x);
    cudaStreamWaitEvent(s1, ev_pack, 0);
    valuemma_kernel<<<dim3(DD / 128, (BB * NN) / 128), 256, MMA_SMEM, s1>>>(bias);
    sumv_mv_kernel<<<BB, DD, 0, s1>>>(W, bias);
    for (int b = 0; b < BB; b++) {
        cudaStreamWaitEvent(s1, ev_cos[b], 0);
        topk_out_kernel<<<NN, 256, 0, s1>>>(out, b);
    }

    cudaEventRecord(ev_join, s1);
    cudaStreamWaitEvent(0, ev_join, 0);
}

// round 16
// speedup vs baseline: 1.7266x; 1.1233x over previous
#include <cuda_runtime.h>
#include <cuda_fp16.h>
#include <cuda_bf16.h>
#include <cstdint>
#include <math.h>

#define BB 4
#define NN 4096
#define DD 256
#define KTOP 64
#define EPSN 1e-12f

#define PACKW 256             // fp16 row
#define NCHUNK 4              // K=256 in 64-element chunks

// ---------------- scratch ----------------
__device__ __nv_bfloat16  g_value[(size_t)BB * NN * DD];
__device__ __half         g_cos  [(size_t)BB * NN * NN];        // fp16 cos (128 MB)
__device__ __half         g_pack [(size_t)BB * NN * PACKW];
__device__ __half         g_Wpack[(size_t)DD * PACKW];
__device__ float          g_norm [(size_t)BB * NN];
__device__ float          g_xsum_part[BB * 16 * DD];
__device__ float          g_sumv[BB * DD];

__device__ __forceinline__ uint32_t smem_to_u32(const void* p) {
    uint32_t a;
    asm("{ .reg .u64 t; cvta.to.shared.u64 t, %1; cvt.u32.u64 %0, t; }" : "=r"(a) : "l"(p));
    return a;
}
__device__ __forceinline__ void ldsm4(uint32_t& r0, uint32_t& r1, uint32_t& r2, uint32_t& r3, uint32_t addr) {
    asm volatile("ldmatrix.sync.aligned.m8n8.x4.shared.b16 {%0,%1,%2,%3}, [%4];"
        : "=r"(r0), "=r"(r1), "=r"(r2), "=r"(r3) : "r"(addr));
}
__device__ __forceinline__ void mma16816(float* d, const uint32_t* a, const uint32_t* b) {
    asm volatile("mma.sync.aligned.m16n8k16.row.col.f32.f16.f16.f32 "
        "{%0,%1,%2,%3}, {%4,%5,%6,%7}, {%8,%9}, {%0,%1,%2,%3};"
        : "+f"(d[0]), "+f"(d[1]), "+f"(d[2]), "+f"(d[3])
        : "r"(a[0]), "r"(a[1]), "r"(a[2]), "r"(a[3]), "r"(b[0]), "r"(b[1]));
}
__device__ __forceinline__ void cp_async16(uint32_t saddr, const void* gptr) {
    asm volatile("cp.async.cg.shared.global [%0], [%1], 16;" :: "r"(saddr), "l"(gptr) : "memory");
}
#define CP_COMMIT() asm volatile("cp.async.commit_group;" ::: "memory")
#define CP_WAIT(N)  asm volatile("cp.async.wait_group %0;" :: "n"(N) : "memory")

// order-preserving 16-bit key for fp16 bits
__device__ __forceinline__ unsigned key16(unsigned h) {
    return (h & 0x8000u) ? ((~h) & 0xFFFFu) : (h | 0x8000u);
}
__device__ __forceinline__ float val_of_key16(unsigned k) {
    unsigned h = (k & 0x8000u) ? (k & 0x7FFFu) : ((~k) & 0xFFFFu);
    __half hv = __ushort_as_half((unsigned short)h);
    return __half2float(hv);
}

// ---------------- 1) normalize + fp16 pack + norm save (+ W pack piggyback) ----------------
__global__ void __launch_bounds__(DD) normalize_pack_kernel(const float* __restrict__ x,
                                                            const float* __restrict__ W)
{
    int row = blockIdx.x;
    int d   = threadIdx.x;
    float v = x[(size_t)row * DD + d];
    float s = v * v;
    __shared__ float red[8];
    #pragma unroll
    for (int o = 16; o; o >>= 1) s += __shfl_xor_sync(0xffffffffu, s, o);
    if ((d & 31) == 0) red[d >> 5] = s;
    __syncthreads();
    if (d < 32) {
        float t = (d < 8) ? red[d] : 0.f;
        #pragma unroll
        for (int o = 4; o; o >>= 1) t += __shfl_xor_sync(0xffffffffu, t, o);
        if (d == 0) red[0] = t;
    }
    __syncthreads();
    float norm = sqrtf(red[0]);
    float nv = v / fmaxf(norm, EPSN);

    g_pack[(size_t)row * PACKW + d] = __float2half(nv);
    if (d == 0) g_norm[row] = norm;

    if (row < DD)
        g_Wpack[(size_t)row * PACKW + d] = __float2half(W[(size_t)row * DD + d]);
}

// ---------------- 1b) per-batch partial column sums of x ----------------
__global__ void __launch_bounds__(DD) xsum_part_kernel(const float* __restrict__ x)
{
    int b = blockIdx.y, c = blockIdx.x, e = threadIdx.x;
    const float* base = x + (size_t)b * NN * DD + (size_t)c * 256 * DD + e;
    float s = 0.f;
    #pragma unroll 8
    for (int n = 0; n < 256; n++) s += base[(size_t)n * DD];
    g_xsum_part[(b * 16 + c) * DD + e] = s;
}

// ---------------- 1c) sumv = (colsum x) @ W^T + N*b  (exact algebra) ----------------
__global__ void __launch_bounds__(DD) sumv_mv_kernel(const float* __restrict__ W,
                                                     const float* __restrict__ bias)
{
    int b = blockIdx.x, t = threadIdx.x;
    __shared__ float xs[DD];
    float s = 0.f;
    #pragma unroll
    for (int c = 0; c < 16; c++) s += g_xsum_part[(b * 16 + c) * DD + t];
    xs[t] = s;
    __syncthreads();
    float acc = 0.f;
    const float4* Wr = (const float4*)&W[(size_t)t * DD];
    #pragma unroll 8
    for (int d4 = 0; d4 < 64; d4++) {
        float4 w = Wr[d4];
        acc += xs[d4 * 4 + 0] * w.x + xs[d4 * 4 + 1] * w.y
             + xs[d4 * 4 + 2] * w.z + xs[d4 * 4 + 3] * w.w;
    }
    g_sumv[b * DD + t] = acc + (float)NN * bias[t];
}

// ---------------- 2) value = norm * (nx @ W^T) + b  -> bf16  (fp16 mma, K=256) ----------------
__global__ void __launch_bounds__(256, 2) valuemma_kernel(const float* __restrict__ bias)
{
    extern __shared__ char smem[];
    const uint32_t sb = smem_to_u32(smem);

    const int tid  = threadIdx.x;
    const int wid  = tid >> 5;
    const int lane = tid & 31;
    const int wm   = wid & 3;
    const int wn   = wid >> 2;
    const int m0   = blockIdx.y * 128;
    const int n0   = blockIdx.x * 128;

    const __half* Agl = g_pack  + (size_t)m0 * PACKW;
    const __half* Bgl = g_Wpack + (size_t)n0 * PACKW;

    const int lr = tid >> 3;
    const int lj = tid & 7;

    auto load_chunk_async = [&](int c, int s) {
        const char* ga = (const char*)Agl + (size_t)c * 128;
        const char* gb = (const char*)Bgl + (size_t)c * 128;
        uint32_t sa = sb + s * 32768;
        uint32_t sbm = sa + 16384;
        #pragma unroll
        for (int k = 0; k < 4; k++) {
            int r = lr + 32 * k;
            uint32_t off = r * 128 + ((lj ^ (r & 7)) << 4);
            cp_async16(sa + off,  ga + (size_t)r * (PACKW * 2) + lj * 16);
            cp_async16(sbm + off, gb + (size_t)r * (PACKW * 2) + lj * 16);
        }
    };

    float acc[2][8][4];
    #pragma unroll
    for (int ia = 0; ia < 2; ia++)
        #pragma unroll
        for (int j = 0; j < 8; j++)
            #pragma unroll
            for (int q = 0; q < 4; q++) acc[ia][j][q] = 0.f;

    const int arow_lo = (lane & 7) + ((lane >> 3) & 1) * 8;
    const int a_cc_add = (lane >> 4);
    const int brow_lo = (lane & 7) + ((lane >> 4) ? 8 : 0);
    const int b_cc_add = ((lane >> 3) & 1);

    load_chunk_async(0, 0); CP_COMMIT();
    load_chunk_async(1, 1); CP_COMMIT();

    for (int c = 0; c < NCHUNK; c++) {
        if (c + 1 < NCHUNK) { CP_WAIT(1); } else { CP_WAIT(0); }
        __syncthreads();
        if (c + 2 < NCHUNK) { load_chunk_async(c + 2, (c + 2) % 3); CP_COMMIT(); }

        const uint32_t abase = sb + (c % 3) * 32768;
        const uint32_t bbase = abase + 16384;

        #pragma unroll
        for (int ks = 0; ks < 4; ks++) {
            uint32_t af[2][4], bf[8][2];
            #pragma unroll
            for (int ia = 0; ia < 2; ia++) {
                int row = wm * 32 + ia * 16 + arow_lo;
                uint32_t cc = 2 * ks + a_cc_add;
                uint32_t addr = abase + row * 128 + ((cc << 4) ^ ((row & 7) << 4));
                ldsm4(af[ia][0], af[ia][1], af[ia][2], af[ia][3], addr);
            }
            #pragma unroll
            for (int L = 0; L < 4; L++) {
                int row = wn * 64 + L * 16 + brow_lo;
                uint32_t cc = 2 * ks + b_cc_add;
                uint32_t addr = bbase + row * 128 + ((cc << 4) ^ ((row & 7) << 4));
                ldsm4(bf[2 * L][0], bf[2 * L][1], bf[2 * L + 1][0], bf[2 * L + 1][1], addr);
            }
            #pragma unroll
            for (int ia = 0; ia < 2; ia++)
                #pragma unroll
                for (int j = 0; j < 8; j++)
                    mma16816(acc[ia][j], af[ia], bf[j]);
        }
    }

    const int g = lane >> 2, q = lane & 3;
    #pragma unroll
    for (int ia = 0; ia < 2; ia++) {
        int row = m0 + wm * 32 + ia * 16 + g;
        float nr0 = __ldg(&g_norm[row]);
        float nr8 = __ldg(&g_norm[row + 8]);
        #pragma unroll
        for (int j = 0; j < 8; j++) {
            int col = n0 + wn * 64 + j * 8 + q * 2;
            float b0 = __ldg(&bias[col]), b1 = __ldg(&bias[col + 1]);
            __nv_bfloat162 v01 = __floats2bfloat162_rn(acc[ia][j][0] * nr0 + b0, acc[ia][j][1] * nr0 + b1);
            __nv_bfloat162 v23 = __floats2bfloat162_rn(acc[ia][j][2] * nr8 + b0, acc[ia][j][3] * nr8 + b1);
            *(__nv_bfloat162*)&g_value[(size_t)row * DD + col]       = v01;
            *(__nv_bfloat162*)&g_value[(size_t)(row + 8) * DD + col] = v23;
        }
    }
}

// ---------------- 4) cos = nx @ nx^T  (fp16 mma, fp16 OUTPUT, per batch, triangle+mirror) ----------------
__global__ void __launch_bounds__(256, 2) cosmma_kernel(__half* __restrict__ C, int b)
{
    extern __shared__ char smem[];
    const uint32_t sb = smem_to_u32(smem);

    const int tid  = threadIdx.x;
    const int wid  = tid >> 5;
    const int lane = tid & 31;
    const int wm   = wid & 3;
    const int wn   = wid >> 2;

    int i  = blockIdx.x;
    int by = (int)((sqrtf(8.f * (float)i + 1.f) - 1.f) * 0.5f);
    while ((by + 1) * (by + 2) / 2 <= i) by++;
    while (by * (by + 1) / 2 > i) by--;
    int bx = i - by * (by + 1) / 2;
    const int m0 = by * 128;
    const int n0 = bx * 128;

    const __half* Agl = g_pack + ((size_t)b * NN + m0) * PACKW;
    const __half* Bgl = g_pack + ((size_t)b * NN + n0) * PACKW;

    const int lr = tid >> 3;
    const int lj = tid & 7;

    auto load_chunk_async = [&](int c, int s) {
        const char* ga = (const char*)Agl + (size_t)c * 128;
        const char* gb = (const char*)Bgl + (size_t)c * 128;
        uint32_t sa = sb + s * 32768;
        uint32_t sbm = sa + 16384;
        #pragma unroll
        for (int k = 0; k < 4; k++) {
            int r = lr + 32 * k;
            uint32_t off = r * 128 + ((lj ^ (r & 7)) << 4);
            cp_async16(sa + off,  ga + (size_t)r * (PACKW * 2) + lj * 16);
            cp_async16(sbm + off, gb + (size_t)r * (PACKW * 2) + lj * 16);
        }
    };

    float acc[2][8][4];
    #pragma unroll
    for (int ia = 0; ia < 2; ia++)
        #pragma unroll
        for (int j = 0; j < 8; j++)
            #pragma unroll
            for (int q = 0; q < 4; q++) acc[ia][j][q] = 0.f;

    const int arow_lo = (lane & 7) + ((lane >> 3) & 1) * 8;
    const int a_cc_add = (lane >> 4);
    const int brow_lo = (lane & 7) + ((lane >> 4) ? 8 : 0);
    const int b_cc_add = ((lane >> 3) & 1);

    load_chunk_async(0, 0); CP_COMMIT();
    load_chunk_async(1, 1); CP_COMMIT();

    for (int c = 0; c < NCHUNK; c++) {
        if (c + 1 < NCHUNK) { CP_WAIT(1); } else { CP_WAIT(0); }
        __syncthreads();
        if (c + 2 < NCHUNK) { load_chunk_async(c + 2, (c + 2) % 3); CP_COMMIT(); }

        const uint32_t abase = sb + (c % 3) * 32768;
        const uint32_t bbase = abase + 16384;

        #pragma unroll
        for (int ks = 0; ks < 4; ks++) {
            uint32_t af[2][4], bf[8][2];
            #pragma unroll
            for (int ia = 0; ia < 2; ia++) {
                int row = wm * 32 + ia * 16 + arow_lo;
                uint32_t cc = 2 * ks + a_cc_add;
                uint32_t addr = abase + row * 128 + ((cc << 4) ^ ((row & 7) << 4));
                ldsm4(af[ia][0], af[ia][1], af[ia][2], af[ia][3], addr);
            }
            #pragma unroll
            for (int L = 0; L < 4; L++) {
                int row = wn * 64 + L * 16 + brow_lo;
                uint32_t cc = 2 * ks + b_cc_add;
                uint32_t addr = bbase + row * 128 + ((cc << 4) ^ ((row & 7) << 4));
                ldsm4(bf[2 * L][0], bf[2 * L][1], bf[2 * L + 1][0], bf[2 * L + 1][1], addr);
            }
            #pragma unroll
            for (int ia = 0; ia < 2; ia++)
                #pragma unroll
                for (int j = 0; j < 8; j++)
                    mma16816(acc[ia][j], af[ia], bf[j]);
        }
    }

    __half* Cb = C + (size_t)b * NN * NN;
    const int g = lane >> 2, q = lane & 3;
    #pragma unroll
    for (int ia = 0; ia < 2; ia++) {
        int row = m0 + wm * 32 + ia * 16 + g;
        #pragma unroll
        for (int j = 0; j < 8; j++) {
            int col = n0 + wn * 64 + j * 8 + q * 2;
            __half2 h01 = __floats2half2_rn(acc[ia][j][0], acc[ia][j][1]);
            __half2 h23 = __floats2half2_rn(acc[ia][j][2], acc[ia][j][3]);
            *(__half2*)&Cb[(size_t)row * NN + col]       = h01;
            *(__half2*)&Cb[(size_t)(row + 8) * NN + col] = h23;
            if (bx != by) {
                Cb[(size_t)col * NN + row]           = __low2half(h01);
                Cb[(size_t)(col + 1) * NN + row]     = __high2half(h01);
                Cb[(size_t)col * NN + row + 8]       = __low2half(h23);
                Cb[(size_t)(col + 1) * NN + row + 8] = __high2half(h23);
            }
        }
    }
}

// ---------------- 5) 2-pass radix-select top-64 on fp16 keys + fused output; per batch ----------------
__global__ void __launch_bounds__(256) topk_out_kernel(float* __restrict__ out, int b)
{
    const int n = blockIdx.x;
    const int t = threadIdx.x;

    __shared__ int      hist[256];
    __shared__ unsigned sh_prefix;
    __shared__ int      sh_krem;
    __shared__ float    red_f[8];
    __shared__ int      sel_idx[KTOP];
    __shared__ unsigned sel_key[KTOP];
    __shared__ float    sel_w[KTOP];
    __shared__ int      eq_idx[128];
    __shared__ int      cnt_gt, cnt_eq;
    __shared__ float    Zsh;

    const __half* row = g_cos + ((size_t)b * NN + n) * NN;

    // 16 fp16 keys per thread, packed in 8 words; key j at idx 16*t+j
    uint32_t kk[8];
    *(uint4*)&kk[0] = ((const uint4*)row)[2 * t];
    *(uint4*)&kk[4] = ((const uint4*)row)[2 * t + 1];
    unsigned kreg[16];
    #pragma unroll
    for (int j = 0; j < 16; j++)
        kreg[j] = key16((kk[j >> 1] >> ((j & 1) * 16)) & 0xFFFFu);

    if (t == 0) { sh_prefix = 0u; sh_krem = KTOP; cnt_gt = 0; cnt_eq = 0; }
    __syncthreads();

    // ---- 2-pass radix over 16-bit keys ----
    #pragma unroll
    for (int d = 1; d >= 0; d--) {
        hist[t] = 0;
        __syncthreads();
        const unsigned prefix = sh_prefix;
        const int krem = sh_krem;
        const int shift = d * 8;
        const unsigned mask = (d == 1) ? 0u : 0xFF00u;
        #pragma unroll
        for (int j = 0; j < 16; j++) {
            unsigned u = kreg[j];
            if ((u & mask) == prefix) atomicAdd(&hist[(u >> shift) & 0xFF], 1);
        }
        __syncthreads();
        if (t < 32) {
            int bins[8], local = 0;
            #pragma unroll
            for (int i2 = 0; i2 < 8; i2++) { bins[i2] = hist[255 - 8 * t - i2]; local += bins[i2]; }
            int excl = local;
            #pragma unroll
            for (int o = 1; o < 32; o <<= 1) {
                int v = __shfl_up_sync(0xffffffffu, excl, o);
                if (t >= o) excl += v;
            }
            excl -= local;
            if (excl < krem && krem <= excl + local) {
                int run = excl, digit = 0, gt_before = excl;
                #pragma unroll
                for (int i2 = 0; i2 < 8; i2++) {
                    if (run + bins[i2] >= krem) { digit = 255 - 8 * t - i2; gt_before = run; break; }
                    run += bins[i2];
                }
                sh_prefix = prefix | ((unsigned)digit << shift);
                sh_krem = krem - gt_before;
            }
        }
        __syncthreads();
    }
    const unsigned ustar = sh_prefix;
    const int r = sh_krem;

    #pragma unroll
    for (int j = 0; j < 16; j++) {
        unsigned u = kreg[j];
        int idx = 16 * t + j;
        if (u > ustar) {
            int p = atomicAdd(&cnt_gt, 1);
            sel_idx[p] = idx;
            sel_key[p] = u;
        } else if (u == ustar) {
            int p = atomicAdd(&cnt_eq, 1);
            if (p < 128) eq_idx[p] = idx;
        }
    }
    __syncthreads();

    const int ngt = cnt_gt;
    if (t == 0) {
        int ne = cnt_eq < 128 ? cnt_eq : 128;
        for (int a = 1; a < ne; a++) {
            int v = eq_idx[a]; int c2 = a - 1;
            while (c2 >= 0 && eq_idx[c2] > v) { eq_idx[c2 + 1] = eq_idx[c2]; c2--; }
            eq_idx[c2 + 1] = v;
        }
        for (int a = 0; a < r; a++) { sel_idx[ngt + a] = eq_idx[a]; sel_key[ngt + a] = ustar; }
    }
    __syncthreads();

    float e_val = 0.f;
    if (t < KTOP) {
        e_val = expf(val_of_key16(sel_key[t]));
        sel_w[t] = e_val - 1.0f;
    }
    float s = e_val;
    #pragma unroll
    for (int o = 16; o; o >>= 1) s += __shfl_xor_sync(0xffffffffu, s, o);
    if ((t & 31) == 0) red_f[t >> 5] = s;
    __syncthreads();
    if (t == 0) {
        float z = (float)(NN - KTOP);
        #pragma unroll
        for (int w = 0; w < 8; w++) z += red_f[w];
        Zsh = z;
    }
    __syncthreads();

    const __nv_bfloat16* Vb = g_value + (size_t)b * NN * DD;
    float acc = g_sumv[b * DD + t];
    const float invZ = 1.0f / Zsh;
    #pragma unroll 8
    for (int k = 0; k < KTOP; k++)
        acc += sel_w[k] * __bfloat162float(Vb[(size_t)sel_idx[k] * DD + t]);
    out[((size_t)b * NN + n) * DD + t] = acc * invZ;
}

// ---------------- launch: two-stream per-batch pipeline ----------------
extern "C" void kernel_launch(void* const* d_in, const int* in_sizes, int n_in,
                              void* d_out, int out_size)
{
    const float* x    = (const float*)d_in[0];
    const float* W    = (const float*)d_in[1];
    const float* bias = (const float*)d_in[2];
    float*       out  = (float*)d_out;

    __half* p_cos;
    cudaGetSymbolAddress((void**)&p_cos, g_cos);

    static bool init_done = false;
    static cudaStream_t s1;
    static cudaEvent_t ev_pack, ev_cos[BB], ev_join;
    if (!init_done) {
        cudaStreamCreateWithFlags(&s1, cudaStreamNonBlocking);
        cudaEventCreateWithFlags(&ev_pack, cudaEventDisableTiming);
        for (int b = 0; b < BB; b++) cudaEventCreateWithFlags(&ev_cos[b], cudaEventDisableTiming);
        cudaEventCreateWithFlags(&ev_join, cudaEventDisableTiming);

        const int SM = 3 * 32768;
        cudaFuncSetAttribute(cosmma_kernel,   cudaFuncAttributeMaxDynamicSharedMemorySize, SM);
        cudaFuncSetAttribute(valuemma_kernel, cudaFuncAttributeMaxDynamicSharedMemorySize, SM);
        init_done = true;
    }
    const int MMA_SMEM = 3 * 32768;
    const int COS_GRID = (NN / 128) * (NN / 128 + 1) / 2;   // 528

    // s0: pack, then cos per batch
    normalize_pack_kernel<<<BB * NN, DD>>>(x, W);
    cudaEventRecord(ev_pack, 0);
    for (int b = 0; b < BB; b++) {
        cosmma_kernel<<<COS_GRID, 256, MMA_SMEM>>>(p_cos, b);
        cudaEventRecord(ev_cos[b], 0);
    }

    // s1: topk prologue, then topk per batch gated on cos events
    xsum_part_kernel<<<dim3(16, BB), DD, 0, s1>>>(x);
    cudaStreamWaitEvent(s1, ev_pack, 0);
    valuemma_kernel<<<dim3(DD / 128, (BB * NN) / 128), 256, MMA_SMEM, s1>>>(bias);
    sumv_mv_kernel<<<BB, DD, 0, s1>>>(W, bias);
    for (int b = 0; b < BB; b++) {
        cudaStreamWaitEvent(s1, ev_cos[b], 0);
        topk_out_kernel<<<NN, 256, 0, s1>>>(out, b);
    }

    cudaEventRecord(ev_join, s1);
    cudaStreamWaitEvent(0, ev_join, 0);
}